// round 12
// baseline (speedup 1.0000x reference)
#include <cuda_runtime.h>
#include <cuda_fp16.h>
#include <cstdint>
#include <math.h>

// ---------------- problem constants ------------------------------------------
#define NTOK 8192
#define CDIM 1024
#define HDIM 2048
#define NEXP 8
#define NPAIR (NTOK * 2)
#define BM 128
#define MT_MAX 136

// ---------------- scratch ----------------------------------------------------
__device__ __half g_xh[(size_t)NTOK * CDIM];              // x in fp16 (per token)
__device__ __half g_wgT[(size_t)NEXP * HDIM * CDIM];
__device__ __half g_wiT[(size_t)NEXP * HDIM * CDIM];
__device__ __half g_woT[(size_t)NEXP * CDIM * HDIM];
__device__ __half g_h[(size_t)NPAIR * HDIM];
__device__ float  g_y[(size_t)NPAIR * CDIM];

__device__ int   g_sel[NTOK * 2];
__device__ float g_selw[NTOK * 2];
__device__ int   g_tok[NPAIR];
__device__ float g_wt[NPAIR];
__device__ int   g_pairidx[NTOK * 2];
__device__ int   g_cnt[NEXP];
__device__ int   g_off[NEXP];
__device__ int   g_tileE[MT_MAX];
__device__ int   g_tileR[MT_MAX];
__device__ int   g_numTiles;

// ---------------- PTX helpers -------------------------------------------------
__device__ __forceinline__ uint32_t smem_u32(const void* p) {
    uint32_t a;
    asm("{ .reg .u64 t; cvta.to.shared.u64 t, %1; cvt.u32.u64 %0, t; }" : "=r"(a) : "l"(p));
    return a;
}
__device__ __forceinline__ void ldsm4(uint32_t* r, uint32_t addr) {
    asm volatile("ldmatrix.sync.aligned.m8n8.x4.shared.b16 {%0,%1,%2,%3}, [%4];"
                 : "=r"(r[0]), "=r"(r[1]), "=r"(r[2]), "=r"(r[3]) : "r"(addr));
}
__device__ __forceinline__ void mma_f16(float* d, const uint32_t* a, uint32_t b0, uint32_t b1) {
    asm volatile("mma.sync.aligned.m16n8k16.row.col.f32.f16.f16.f32 "
                 "{%0,%1,%2,%3}, {%4,%5,%6,%7}, {%8,%9}, {%0,%1,%2,%3};"
                 : "+f"(d[0]), "+f"(d[1]), "+f"(d[2]), "+f"(d[3])
                 : "r"(a[0]), "r"(a[1]), "r"(a[2]), "r"(a[3]), "r"(b0), "r"(b1));
}
#define CP_ASYNC16(dst, src, sz) \
    asm volatile("cp.async.cg.shared.global [%0], [%1], 16, %2;" :: "r"(dst), "l"(src), "r"(sz) : "memory")
#define CP_COMMIT() asm volatile("cp.async.commit_group;" ::: "memory")
#define CP_WAIT(n)  asm volatile("cp.async.wait_group %0;" :: "n"(n) : "memory")

// ---------------- gating -----------------------------------------------------
__global__ void gate_kernel(const float* __restrict__ x, const float* __restrict__ wgate) {
    int warp = (blockIdx.x * blockDim.x + threadIdx.x) >> 5;
    int lane = threadIdx.x & 31;
    if (warp >= NTOK) return;
    const float* xr = x + (size_t)warp * CDIM;
    float acc[NEXP];
#pragma unroll
    for (int e = 0; e < NEXP; e++) acc[e] = 0.f;
    for (int i = lane * 4; i < CDIM; i += 128) {
        float4 xv = *(const float4*)(xr + i);
        float xs[4] = {xv.x, xv.y, xv.z, xv.w};
#pragma unroll
        for (int j = 0; j < 4; j++) {
            const float* wr = wgate + (size_t)(i + j) * NEXP;
#pragma unroll
            for (int e = 0; e < NEXP; e++) acc[e] += xs[j] * wr[e];
        }
    }
#pragma unroll
    for (int e = 0; e < NEXP; e++)
#pragma unroll
        for (int d = 16; d > 0; d >>= 1) acc[e] += __shfl_down_sync(0xffffffffu, acc[e], d);
    if (lane == 0) {
        float m = acc[0];
#pragma unroll
        for (int e = 1; e < NEXP; e++) m = fmaxf(m, acc[e]);
        float p[NEXP]; float s = 0.f;
#pragma unroll
        for (int e = 0; e < NEXP; e++) { p[e] = expf(acc[e] - m); s += p[e]; }
        float inv = 1.f / s;
#pragma unroll
        for (int e = 0; e < NEXP; e++) p[e] *= inv;
        int i1 = 0;
#pragma unroll
        for (int e = 1; e < NEXP; e++) if (p[e] > p[i1]) i1 = e;
        int i2 = (i1 == 0) ? 1 : 0;
#pragma unroll
        for (int e = 0; e < NEXP; e++) if (e != i1 && p[e] > p[i2]) i2 = e;
        g_sel[2 * warp] = i1;     g_selw[2 * warp] = p[i1];
        g_sel[2 * warp + 1] = i2; g_selw[2 * warp + 1] = p[i2];
    }
}

// ---------------- routing: parallel count / offsets / stable place ------------
__global__ void cnt_kernel() {
    int e = blockIdx.x, tid = threadIdx.x, lane = tid & 31, wid = tid >> 5;
    __shared__ int red[32];
    int c = 0;
    for (int t = tid; t < NTOK; t += 1024)
        c += (g_sel[2 * t] == e) + (g_sel[2 * t + 1] == e);
#pragma unroll
    for (int d = 16; d > 0; d >>= 1) c += __shfl_down_sync(0xffffffffu, c, d);
    if (lane == 0) red[wid] = c;
    __syncthreads();
    if (wid == 0) {
        int v = red[lane];
#pragma unroll
        for (int d = 16; d > 0; d >>= 1) v += __shfl_down_sync(0xffffffffu, v, d);
        if (lane == 0) g_cnt[e] = v;
    }
}

__global__ void offs_kernel() {
    int o = 0, nt = 0;
    for (int e = 0; e < NEXP; e++) {
        g_off[e] = o;
        for (int r = 0; r < g_cnt[e]; r += BM) { g_tileE[nt] = e; g_tileR[nt] = r; nt++; }
        o += g_cnt[e];
    }
    g_numTiles = nt;
}

__global__ void place_kernel() {
    int e = blockIdx.x;
    __shared__ int wsum[32];
    __shared__ int carry;
    int tid = threadIdx.x, lane = tid & 31, wid = tid >> 5;
    if (tid == 0) carry = 0;
    __syncthreads();
    int base_off = g_off[e];
    for (int base = 0; base < NTOK; base += 1024) {
        int t = base + tid;
        int slot = (g_sel[2 * t] == e) ? 0 : ((g_sel[2 * t + 1] == e) ? 1 : -1);
        int f = (slot >= 0) ? 1 : 0;
        int v = f;
#pragma unroll
        for (int d = 1; d < 32; d <<= 1) {
            int u = __shfl_up_sync(0xffffffffu, v, d);
            if (lane >= d) v += u;
        }
        if (lane == 31) wsum[wid] = v;
        __syncthreads();
        int wbase = 0, tot = 0;
#pragma unroll
        for (int w = 0; w < 32; w++) { if (w < wid) wbase += wsum[w]; tot += wsum[w]; }
        if (f) {
            int p = base_off + carry + wbase + v - 1;
            g_tok[p] = t;
            g_wt[p] = g_selw[2 * t + slot];
            g_pairidx[2 * t + slot] = p;
        }
        __syncthreads();
        if (tid == 0) carry += tot;
        __syncthreads();
    }
}

// ---------------- x -> fp16 (per token, no pair duplication) ------------------
__global__ void xconv_kernel(const float* __restrict__ x) {
    size_t i = (size_t)blockIdx.x * 512 + threadIdx.x;
    float2 v = ((const float2*)x)[i];
    ((__half2*)g_xh)[i] = __floats2half2_rn(v.x, v.y);
}

// ---------------- weight transpose + fp16 (64K x 32S tiles, half2 stores) -----
template <int W>
__global__ void tconv_kernel(const float* __restrict__ src, int K, int S) {
    __half* dst = (W == 0) ? g_wgT : (W == 1) ? g_wiT : g_woT;
    __shared__ float t[64][33];
    int e = blockIdx.z;
    int k0 = blockIdx.x * 64, s0 = blockIdx.y * 32;
    const float* sp = src + (size_t)e * K * S;
    int tx = threadIdx.x, ty = threadIdx.y;     // (32, 8)
#pragma unroll
    for (int j = 0; j < 64; j += 8)
        t[ty + j][tx] = sp[(size_t)(k0 + ty + j) * S + s0 + tx];
    __syncthreads();
    size_t dbase = (size_t)e * S * K;
#pragma unroll
    for (int j = 0; j < 32; j += 8) {
        int s = s0 + ty + j;
        __half2 h = __floats2half2_rn(t[tx * 2][ty + j], t[tx * 2 + 1][ty + j]);
        *(__half2*)&dst[dbase + (size_t)s * K + k0 + tx * 2] = h;
    }
}

// ---------------- fp16 mma GEMM, 128x128 tile, 3-stage cp.async ---------------
#define PITCHB 80
#define PLANEB (128 * PITCHB)   // 10240
#define STAGES 3

template <int MODE>
__global__ void __launch_bounds__(512, 1)
moe_hmma() {
    constexpr int K = (MODE == 0) ? CDIM : HDIM;
    constexpr int KT = K / 32;
    constexpr int NW = (MODE == 0) ? 2 : 1;
    constexpr int STAGEB = (1 + NW) * PLANEB;

    extern __shared__ char smem[];
    uint32_t sb = smem_u32(smem);

    int bx = blockIdx.x;
    if (bx >= g_numTiles) return;
    int by = blockIdx.y;
    int e = g_tileE[bx], r0 = g_tileR[bx], off = g_off[e];
    int rowsLeft = g_cnt[e] - r0;
    if (rowsLeft > 128) rowsLeft = 128;
    int nb = by * 128;

    int tid = threadIdx.x, wid = tid >> 5, lane = tid & 31;
    int WM = wid & 3, WN = wid >> 2;
    int gq = lane >> 2, tg = lane & 3;

    const __half* srcB[2];
    if (MODE == 0) {
        srcB[0] = g_wgT + ((size_t)e * HDIM + nb) * CDIM;
        srcB[1] = g_wiT + ((size_t)e * HDIM + nb) * CDIM;
    } else {
        srcB[0] = g_woT + ((size_t)e * CDIM + nb) * HDIM;
    }

    int lrow = tid >> 2, lch = tid & 3;
    bool aval = lrow < rowsLeft;
    int ra = aval ? lrow : 0;
    const __half* aRowPtr;
    if (MODE == 0) {
        int tok = g_tok[off + r0 + ra];
        aRowPtr = g_xh + (size_t)tok * CDIM;
    } else {
        aRowPtr = g_h + (size_t)(off + r0 + ra) * HDIM;
    }
    uint32_t szA = aval ? 16u : 0u;

    auto load_buf = [&](int buf, int kc) {
        uint32_t base = sb + buf * STAGEB;
        int k0 = kc * 32;
        uint32_t doff = lrow * PITCHB + lch * 16;
        CP_ASYNC16(base + doff, aRowPtr + k0 + lch * 8, szA);
#pragma unroll
        for (int p = 0; p < NW; p++)
            CP_ASYNC16(base + (1 + p) * PLANEB + doff,
                       srcB[p] + (size_t)lrow * K + k0 + lch * 8, 16u);
        CP_COMMIT();
    };

    float acc[NW][2][4][4];
#pragma unroll
    for (int w = 0; w < NW; w++)
#pragma unroll
        for (int a = 0; a < 2; a++)
#pragma unroll
            for (int b = 0; b < 4; b++)
#pragma unroll
                for (int c = 0; c < 4; c++) acc[w][a][b][c] = 0.f;

    load_buf(0, 0);
    load_buf(1, 1);

    uint32_t aRowOff = (WM * 32 + (lane & 15)) * PITCHB + (lane >> 4) * 16;
    uint32_t bRowOff = (WN * 32 + (lane & 15)) * PITCHB + (lane >> 4) * 16;

    int cb = 0;
    for (int kc = 0; kc < KT; kc++) {
        if (kc + 1 < KT) { CP_WAIT(1); } else { CP_WAIT(0); }
        __syncthreads();
        if (kc + 2 < KT) {
            int lb = cb + 2; if (lb >= STAGES) lb -= STAGES;
            load_buf(lb, kc + 2);
        }

        uint32_t base = sb + cb * STAGEB;
#pragma unroll
        for (int ks = 0; ks < 2; ks++) {
            uint32_t kOff = ks * 32;
            uint32_t a[2][4];
#pragma unroll
            for (int mi = 0; mi < 2; mi++)
                ldsm4(a[mi], base + aRowOff + mi * 16 * PITCHB + kOff);
#pragma unroll
            for (int w = 0; w < NW; w++) {
                uint32_t b[2][4];
                uint32_t bBase = base + (1 + w) * PLANEB;
#pragma unroll
                for (int ng = 0; ng < 2; ng++)
                    ldsm4(b[ng], bBase + bRowOff + ng * 16 * PITCHB + kOff);
#pragma unroll
                for (int mi = 0; mi < 2; mi++)
#pragma unroll
                    for (int nj = 0; nj < 4; nj++) {
                        int ng = nj >> 1, ix = nj & 1;
                        mma_f16(acc[w][mi][nj], a[mi], b[ng][ix], b[ng][ix + 2]);
                    }
            }
        }
        cb++; if (cb >= STAGES) cb = 0;
        __syncthreads();
    }

    // ---- epilogue ----
    int grb = off + r0;
#pragma unroll
    for (int mi = 0; mi < 2; mi++) {
#pragma unroll
        for (int half = 0; half < 2; half++) {
            int r = WM * 32 + mi * 16 + gq + half * 8;
            if (r >= rowsLeft) continue;
            size_t grow = (size_t)(grb + r);
#pragma unroll
            for (int nj = 0; nj < 4; nj++) {
                int c = nb + WN * 32 + nj * 8 + tg * 2;
                if (MODE == 0) {
                    float gt0 = acc[0][mi][nj][half * 2 + 0];
                    float gt1 = acc[0][mi][nj][half * 2 + 1];
                    float up0 = acc[1][mi][nj][half * 2 + 0];
                    float up1 = acc[1][mi][nj][half * 2 + 1];
                    float h0 = up0 * gt0 / (1.f + __expf(-gt0));
                    float h1 = up1 * gt1 / (1.f + __expf(-gt1));
                    __half ph0 = __float2half_rn(h0);
                    __half ph1 = __float2half_rn(h1);
                    uint32_t pk = ((uint32_t)__half_as_ushort(ph1) << 16) | __half_as_ushort(ph0);
                    *(uint32_t*)&g_h[grow * HDIM + c] = pk;
                } else {
                    float d0 = acc[0][mi][nj][half * 2 + 0];
                    float d1 = acc[0][mi][nj][half * 2 + 1];
                    *(float2*)&g_y[grow * CDIM + c] = make_float2(d0, d1);
                }
            }
        }
    }
}

// ---------------- combine ----------------------------------------------------
__global__ void combine_kernel(float* __restrict__ out) {
    int gid = blockIdx.x * blockDim.x + threadIdx.x;
    int t = gid >> 8;
    int c4 = (gid & 255) * 4;
    int p0 = g_pairidx[2 * t], p1 = g_pairidx[2 * t + 1];
    float w0 = g_wt[p0], w1 = g_wt[p1];
    float4 y0 = *(const float4*)&g_y[(size_t)p0 * CDIM + c4];
    float4 y1 = *(const float4*)&g_y[(size_t)p1 * CDIM + c4];
    float4 o;
    o.x = w0 * y0.x + w1 * y1.x;
    o.y = w0 * y0.y + w1 * y1.y;
    o.z = w0 * y0.z + w1 * y1.z;
    o.w = w0 * y0.w + w1 * y1.w;
    *(float4*)(out + (size_t)t * CDIM + c4) = o;
}

// ---------------- launch (stream-forked graph) --------------------------------
#define SMEM0 (STAGES * 3 * PLANEB)   // 92160
#define SMEM2 (STAGES * 2 * PLANEB)   // 61440

extern "C" void kernel_launch(void* const* d_in, const int* in_sizes, int n_in,
                              void* d_out, int out_size) {
    const float* x      = (const float*)d_in[0];
    const float* w_gate = (const float*)d_in[1];
    const float* wi     = (const float*)d_in[2];
    const float* wg     = (const float*)d_in[3];
    const float* wo     = (const float*)d_in[4];
    float* out = (float*)d_out;

    // one-time host-side objects (no device memory)
    static cudaStream_t sB = nullptr, sC = nullptr;
    static cudaEvent_t evFork = nullptr, evB = nullptr, evC = nullptr;
    if (sB == nullptr) {
        cudaStreamCreateWithFlags(&sB, cudaStreamNonBlocking);
        cudaStreamCreateWithFlags(&sC, cudaStreamNonBlocking);
        cudaEventCreateWithFlags(&evFork, cudaEventDisableTiming);
        cudaEventCreateWithFlags(&evB, cudaEventDisableTiming);
        cudaEventCreateWithFlags(&evC, cudaEventDisableTiming);
        cudaFuncSetAttribute(moe_hmma<0>, cudaFuncAttributeMaxDynamicSharedMemorySize, SMEM0);
        cudaFuncSetAttribute(moe_hmma<2>, cudaFuncAttributeMaxDynamicSharedMemorySize, SMEM2);
    }

    // fork: weight conversions run concurrently with routing chain
    cudaEventRecord(evFork, 0);
    cudaStreamWaitEvent(sB, evFork, 0);
    cudaStreamWaitEvent(sC, evFork, 0);

    dim3 tb(32, 8);
    tconv_kernel<0><<<dim3(CDIM / 64, HDIM / 32, NEXP), tb, 0, sB>>>(wg, CDIM, HDIM);
    tconv_kernel<1><<<dim3(CDIM / 64, HDIM / 32, NEXP), tb, 0, sB>>>(wi, CDIM, HDIM);
    cudaEventRecord(evB, sB);
    tconv_kernel<2><<<dim3(HDIM / 64, CDIM / 32, NEXP), tb, 0, sC>>>(wo, HDIM, CDIM);
    cudaEventRecord(evC, sC);

    // routing + activation conversion on the main stream
    gate_kernel<<<NTOK / 8, 256>>>(x, w_gate);
    cnt_kernel<<<NEXP, 1024>>>();
    offs_kernel<<<1, 1>>>();
    place_kernel<<<NEXP, 1024>>>();
    xconv_kernel<<<NTOK * CDIM / 1024, 512>>>(x);

    // join wg/wi conversion, run fused gate+up GEMM (tconv<2> overlaps with it)
    cudaStreamWaitEvent(0, evB, 0);
    moe_hmma<0><<<dim3(MT_MAX, HDIM / 128), 512, SMEM0>>>();

    // join wo conversion, run down GEMM
    cudaStreamWaitEvent(0, evC, 0);
    moe_hmma<2><<<dim3(MT_MAX, CDIM / 128), 512, SMEM2>>>();

    combine_kernel<<<NTOK * (CDIM / 4) / 256, 256>>>(out);
}

// round 13
// speedup vs baseline: 1.2363x; 1.2363x over previous
#include <cuda_runtime.h>
#include <cuda_fp16.h>
#include <cstdint>
#include <math.h>

// ---------------- problem constants ------------------------------------------
#define NTOK 8192
#define CDIM 1024
#define HDIM 2048
#define NEXP 8
#define NPAIR (NTOK * 2)
#define BM 128
#define MT_MAX 136

// ---------------- scratch ----------------------------------------------------
__device__ __half g_xh[(size_t)NTOK * CDIM];
__device__ __half g_wgT[(size_t)NEXP * HDIM * CDIM];
__device__ __half g_wiT[(size_t)NEXP * HDIM * CDIM];
__device__ __half g_woT[(size_t)NEXP * CDIM * HDIM];
__device__ __half g_h[(size_t)NPAIR * HDIM];
__device__ float  g_y[(size_t)NPAIR * CDIM];

__device__ int   g_sel[NTOK * 2];
__device__ float g_selw[NTOK * 2];
__device__ int   g_tok[NPAIR];
__device__ float g_wt[NPAIR];
__device__ int   g_pairidx[NTOK * 2];
__device__ int   g_cnt[NEXP];
__device__ int   g_off[NEXP];
__device__ int   g_tileE[MT_MAX];
__device__ int   g_tileR[MT_MAX];
__device__ int   g_numTiles;

// ---------------- PTX helpers -------------------------------------------------
__device__ __forceinline__ uint32_t smem_u32(const void* p) {
    uint32_t a;
    asm("{ .reg .u64 t; cvta.to.shared.u64 t, %1; cvt.u32.u64 %0, t; }" : "=r"(a) : "l"(p));
    return a;
}
__device__ __forceinline__ void ldsm4(uint32_t* r, uint32_t addr) {
    asm volatile("ldmatrix.sync.aligned.m8n8.x4.shared.b16 {%0,%1,%2,%3}, [%4];"
                 : "=r"(r[0]), "=r"(r[1]), "=r"(r[2]), "=r"(r[3]) : "r"(addr));
}
__device__ __forceinline__ void mma_f16(float* d, const uint32_t* a, uint32_t b0, uint32_t b1) {
    asm volatile("mma.sync.aligned.m16n8k16.row.col.f32.f16.f16.f32 "
                 "{%0,%1,%2,%3}, {%4,%5,%6,%7}, {%8,%9}, {%0,%1,%2,%3};"
                 : "+f"(d[0]), "+f"(d[1]), "+f"(d[2]), "+f"(d[3])
                 : "r"(a[0]), "r"(a[1]), "r"(a[2]), "r"(a[3]), "r"(b0), "r"(b1));
}
#define CP_ASYNC16(dst, src, sz) \
    asm volatile("cp.async.cg.shared.global [%0], [%1], 16, %2;" :: "r"(dst), "l"(src), "r"(sz) : "memory")
#define CP_COMMIT() asm volatile("cp.async.commit_group;" ::: "memory")
#define CP_WAIT(n)  asm volatile("cp.async.wait_group %0;" :: "n"(n) : "memory")

// ---------------- gating (smem-cached transposed wgate) -----------------------
#define WPITCH 1028
__global__ void gate_kernel(const float* __restrict__ x, const float* __restrict__ wgate) {
    __shared__ float swT[NEXP * WPITCH];     // ~32.9 KB
    int tid = threadIdx.x;
    // transpose wgate [C][E] -> swT[e][c] (coalesced reads; conflict-free stores)
    for (int i = tid; i < CDIM * NEXP; i += 256) {
        int c = i >> 3, e = i & 7;
        swT[e * WPITCH + c] = wgate[i];
    }
    __syncthreads();

    int warp = blockIdx.x * 8 + (tid >> 5);
    int lane = tid & 31;
    const float* xr = x + (size_t)warp * CDIM;

    float acc[NEXP];
#pragma unroll
    for (int e = 0; e < NEXP; e++) acc[e] = 0.f;
#pragma unroll
    for (int i = lane * 4; i < CDIM; i += 128) {
        float4 xv = *(const float4*)(xr + i);
#pragma unroll
        for (int e = 0; e < NEXP; e++) {
            float4 wv = *(const float4*)&swT[e * WPITCH + i];
            acc[e] += xv.x * wv.x + xv.y * wv.y + xv.z * wv.z + xv.w * wv.w;
        }
    }
#pragma unroll
    for (int e = 0; e < NEXP; e++)
#pragma unroll
        for (int d = 16; d > 0; d >>= 1) acc[e] += __shfl_down_sync(0xffffffffu, acc[e], d);
    if (lane == 0) {
        float m = acc[0];
#pragma unroll
        for (int e = 1; e < NEXP; e++) m = fmaxf(m, acc[e]);
        float p[NEXP]; float s = 0.f;
#pragma unroll
        for (int e = 0; e < NEXP; e++) { p[e] = expf(acc[e] - m); s += p[e]; }
        float inv = 1.f / s;
#pragma unroll
        for (int e = 0; e < NEXP; e++) p[e] *= inv;
        int i1 = 0;
#pragma unroll
        for (int e = 1; e < NEXP; e++) if (p[e] > p[i1]) i1 = e;
        int i2 = (i1 == 0) ? 1 : 0;
#pragma unroll
        for (int e = 0; e < NEXP; e++) if (e != i1 && p[e] > p[i2]) i2 = e;
        g_sel[2 * warp] = i1;     g_selw[2 * warp] = p[i1];
        g_sel[2 * warp + 1] = i2; g_selw[2 * warp + 1] = p[i2];
    }
}

// ---------------- routing: parallel count / offsets / stable place ------------
__global__ void cnt_kernel() {
    int e = blockIdx.x, tid = threadIdx.x, lane = tid & 31, wid = tid >> 5;
    __shared__ int red[32];
    int c = 0;
    for (int t = tid; t < NTOK; t += 1024)
        c += (g_sel[2 * t] == e) + (g_sel[2 * t + 1] == e);
#pragma unroll
    for (int d = 16; d > 0; d >>= 1) c += __shfl_down_sync(0xffffffffu, c, d);
    if (lane == 0) red[wid] = c;
    __syncthreads();
    if (wid == 0) {
        int v = red[lane];
#pragma unroll
        for (int d = 16; d > 0; d >>= 1) v += __shfl_down_sync(0xffffffffu, v, d);
        if (lane == 0) g_cnt[e] = v;
    }
}

__global__ void offs_kernel() {
    int o = 0, nt = 0;
    for (int e = 0; e < NEXP; e++) {
        g_off[e] = o;
        for (int r = 0; r < g_cnt[e]; r += BM) { g_tileE[nt] = e; g_tileR[nt] = r; nt++; }
        o += g_cnt[e];
    }
    g_numTiles = nt;
}

__global__ void place_kernel() {
    int e = blockIdx.x;
    __shared__ int wsum[32];
    __shared__ int carry;
    int tid = threadIdx.x, lane = tid & 31, wid = tid >> 5;
    if (tid == 0) carry = 0;
    __syncthreads();
    int base_off = g_off[e];
    for (int base = 0; base < NTOK; base += 1024) {
        int t = base + tid;
        int slot = (g_sel[2 * t] == e) ? 0 : ((g_sel[2 * t + 1] == e) ? 1 : -1);
        int f = (slot >= 0) ? 1 : 0;
        int v = f;
#pragma unroll
        for (int d = 1; d < 32; d <<= 1) {
            int u = __shfl_up_sync(0xffffffffu, v, d);
            if (lane >= d) v += u;
        }
        if (lane == 31) wsum[wid] = v;
        __syncthreads();
        int wbase = 0, tot = 0;
#pragma unroll
        for (int w = 0; w < 32; w++) { if (w < wid) wbase += wsum[w]; tot += wsum[w]; }
        if (f) {
            int p = base_off + carry + wbase + v - 1;
            g_tok[p] = t;
            g_wt[p] = g_selw[2 * t + slot];
            g_pairidx[2 * t + slot] = p;
        }
        __syncthreads();
        if (tid == 0) carry += tot;
        __syncthreads();
    }
}

// ---------------- x -> fp16 ----------------------------------------------------
__global__ void xconv_kernel(const float* __restrict__ x) {
    size_t i = (size_t)blockIdx.x * 512 + threadIdx.x;
    float2 v = ((const float2*)x)[i];
    ((__half2*)g_xh)[i] = __floats2half2_rn(v.x, v.y);
}

// ---------------- weight transpose + fp16 -------------------------------------
template <int W>
__global__ void tconv_kernel(const float* __restrict__ src, int K, int S) {
    __half* dst = (W == 0) ? g_wgT : (W == 1) ? g_wiT : g_woT;
    __shared__ float t[64][33];
    int e = blockIdx.z;
    int k0 = blockIdx.x * 64, s0 = blockIdx.y * 32;
    const float* sp = src + (size_t)e * K * S;
    int tx = threadIdx.x, ty = threadIdx.y;
#pragma unroll
    for (int j = 0; j < 64; j += 8)
        t[ty + j][tx] = sp[(size_t)(k0 + ty + j) * S + s0 + tx];
    __syncthreads();
    size_t dbase = (size_t)e * S * K;
#pragma unroll
    for (int j = 0; j < 32; j += 8) {
        int s = s0 + ty + j;
        __half2 h = __floats2half2_rn(t[tx * 2][ty + j], t[tx * 2 + 1][ty + j]);
        *(__half2*)&dst[dbase + (size_t)s * K + k0 + tx * 2] = h;
    }
}

// ---------------- fp16 mma GEMM, 128x128 tile, 3-stage cp.async ---------------
#define PITCHB 80
#define PLANEB (128 * PITCHB)
#define STAGES 3

template <int MODE>
__global__ void __launch_bounds__(512, 1)
moe_hmma() {
    constexpr int K = (MODE == 0) ? CDIM : HDIM;
    constexpr int KT = K / 32;
    constexpr int NW = (MODE == 0) ? 2 : 1;
    constexpr int STAGEB = (1 + NW) * PLANEB;

    extern __shared__ char smem[];
    uint32_t sb = smem_u32(smem);

    int bx = blockIdx.x;
    if (bx >= g_numTiles) return;
    int by = blockIdx.y;
    int e = g_tileE[bx], r0 = g_tileR[bx], off = g_off[e];
    int rowsLeft = g_cnt[e] - r0;
    if (rowsLeft > 128) rowsLeft = 128;
    int nb = by * 128;

    int tid = threadIdx.x, wid = tid >> 5, lane = tid & 31;
    int WM = wid & 3, WN = wid >> 2;
    int gq = lane >> 2, tg = lane & 3;

    const __half* srcB[2];
    if (MODE == 0) {
        srcB[0] = g_wgT + ((size_t)e * HDIM + nb) * CDIM;
        srcB[1] = g_wiT + ((size_t)e * HDIM + nb) * CDIM;
    } else {
        srcB[0] = g_woT + ((size_t)e * CDIM + nb) * HDIM;
    }

    int lrow = tid >> 2, lch = tid & 3;
    bool aval = lrow < rowsLeft;
    int ra = aval ? lrow : 0;
    const __half* aRowPtr;
    if (MODE == 0) {
        int tok = g_tok[off + r0 + ra];
        aRowPtr = g_xh + (size_t)tok * CDIM;
    } else {
        aRowPtr = g_h + (size_t)(off + r0 + ra) * HDIM;
    }
    uint32_t szA = aval ? 16u : 0u;

    auto load_buf = [&](int buf, int kc) {
        uint32_t base = sb + buf * STAGEB;
        int k0 = kc * 32;
        uint32_t doff = lrow * PITCHB + lch * 16;
        CP_ASYNC16(base + doff, aRowPtr + k0 + lch * 8, szA);
#pragma unroll
        for (int p = 0; p < NW; p++)
            CP_ASYNC16(base + (1 + p) * PLANEB + doff,
                       srcB[p] + (size_t)lrow * K + k0 + lch * 8, 16u);
        CP_COMMIT();
    };

    float acc[NW][2][4][4];
#pragma unroll
    for (int w = 0; w < NW; w++)
#pragma unroll
        for (int a = 0; a < 2; a++)
#pragma unroll
            for (int b = 0; b < 4; b++)
#pragma unroll
                for (int c = 0; c < 4; c++) acc[w][a][b][c] = 0.f;

    load_buf(0, 0);
    load_buf(1, 1);

    uint32_t aRowOff = (WM * 32 + (lane & 15)) * PITCHB + (lane >> 4) * 16;
    uint32_t bRowOff = (WN * 32 + (lane & 15)) * PITCHB + (lane >> 4) * 16;

    int cb = 0;
    for (int kc = 0; kc < KT; kc++) {
        if (kc + 1 < KT) { CP_WAIT(1); } else { CP_WAIT(0); }
        __syncthreads();
        if (kc + 2 < KT) {
            int lb = cb + 2; if (lb >= STAGES) lb -= STAGES;
            load_buf(lb, kc + 2);
        }

        uint32_t base = sb + cb * STAGEB;
#pragma unroll
        for (int ks = 0; ks < 2; ks++) {
            uint32_t kOff = ks * 32;
            uint32_t a[2][4];
#pragma unroll
            for (int mi = 0; mi < 2; mi++)
                ldsm4(a[mi], base + aRowOff + mi * 16 * PITCHB + kOff);
#pragma unroll
            for (int w = 0; w < NW; w++) {
                uint32_t b[2][4];
                uint32_t bBase = base + (1 + w) * PLANEB;
#pragma unroll
                for (int ng = 0; ng < 2; ng++)
                    ldsm4(b[ng], bBase + bRowOff + ng * 16 * PITCHB + kOff);
#pragma unroll
                for (int mi = 0; mi < 2; mi++)
#pragma unroll
                    for (int nj = 0; nj < 4; nj++) {
                        int ng = nj >> 1, ix = nj & 1;
                        mma_f16(acc[w][mi][nj], a[mi], b[ng][ix], b[ng][ix + 2]);
                    }
            }
        }
        cb++; if (cb >= STAGES) cb = 0;
        __syncthreads();
    }

    // ---- epilogue ----
    int grb = off + r0;
#pragma unroll
    for (int mi = 0; mi < 2; mi++) {
#pragma unroll
        for (int half = 0; half < 2; half++) {
            int r = WM * 32 + mi * 16 + gq + half * 8;
            if (r >= rowsLeft) continue;
            size_t grow = (size_t)(grb + r);
#pragma unroll
            for (int nj = 0; nj < 4; nj++) {
                int c = nb + WN * 32 + nj * 8 + tg * 2;
                if (MODE == 0) {
                    float gt0 = acc[0][mi][nj][half * 2 + 0];
                    float gt1 = acc[0][mi][nj][half * 2 + 1];
                    float up0 = acc[1][mi][nj][half * 2 + 0];
                    float up1 = acc[1][mi][nj][half * 2 + 1];
                    float h0 = up0 * gt0 / (1.f + __expf(-gt0));
                    float h1 = up1 * gt1 / (1.f + __expf(-gt1));
                    __half ph0 = __float2half_rn(h0);
                    __half ph1 = __float2half_rn(h1);
                    uint32_t pk = ((uint32_t)__half_as_ushort(ph1) << 16) | __half_as_ushort(ph0);
                    *(uint32_t*)&g_h[grow * HDIM + c] = pk;
                } else {
                    float d0 = acc[0][mi][nj][half * 2 + 0];
                    float d1 = acc[0][mi][nj][half * 2 + 1];
                    *(float2*)&g_y[grow * CDIM + c] = make_float2(d0, d1);
                }
            }
        }
    }
}

// ---------------- combine ----------------------------------------------------
__global__ void combine_kernel(float* __restrict__ out) {
    int gid = blockIdx.x * blockDim.x + threadIdx.x;
    int t = gid >> 8;
    int c4 = (gid & 255) * 4;
    int p0 = g_pairidx[2 * t], p1 = g_pairidx[2 * t + 1];
    float w0 = g_wt[p0], w1 = g_wt[p1];
    float4 y0 = *(const float4*)&g_y[(size_t)p0 * CDIM + c4];
    float4 y1 = *(const float4*)&g_y[(size_t)p1 * CDIM + c4];
    float4 o;
    o.x = w0 * y0.x + w1 * y1.x;
    o.y = w0 * y0.y + w1 * y1.y;
    o.z = w0 * y0.z + w1 * y1.z;
    o.w = w0 * y0.w + w1 * y1.w;
    *(float4*)(out + (size_t)t * CDIM + c4) = o;
}

// ---------------- launch (stream-forked graph) --------------------------------
#define SMEM0 (STAGES * 3 * PLANEB)   // 92160
#define SMEM2 (STAGES * 2 * PLANEB)   // 61440

extern "C" void kernel_launch(void* const* d_in, const int* in_sizes, int n_in,
                              void* d_out, int out_size) {
    const float* x      = (const float*)d_in[0];
    const float* w_gate = (const float*)d_in[1];
    const float* wi     = (const float*)d_in[2];
    const float* wg     = (const float*)d_in[3];
    const float* wo     = (const float*)d_in[4];
    float* out = (float*)d_out;

    static cudaStream_t sB = nullptr, sC = nullptr;
    static cudaEvent_t evFork = nullptr, evB = nullptr, evC = nullptr;
    if (sB == nullptr) {
        cudaStreamCreateWithFlags(&sB, cudaStreamNonBlocking);
        cudaStreamCreateWithFlags(&sC, cudaStreamNonBlocking);
        cudaEventCreateWithFlags(&evFork, cudaEventDisableTiming);
        cudaEventCreateWithFlags(&evB, cudaEventDisableTiming);
        cudaEventCreateWithFlags(&evC, cudaEventDisableTiming);
        cudaFuncSetAttribute(moe_hmma<0>, cudaFuncAttributeMaxDynamicSharedMemorySize, SMEM0);
        cudaFuncSetAttribute(moe_hmma<2>, cudaFuncAttributeMaxDynamicSharedMemorySize, SMEM2);
    }

    // fork: weight/activation conversions run concurrently with routing chain
    cudaEventRecord(evFork, 0);
    cudaStreamWaitEvent(sB, evFork, 0);
    cudaStreamWaitEvent(sC, evFork, 0);

    dim3 tb(32, 8);
    xconv_kernel<<<NTOK * CDIM / 1024, 512, 0, sB>>>(x);
    tconv_kernel<0><<<dim3(CDIM / 64, HDIM / 32, NEXP), tb, 0, sB>>>(wg, CDIM, HDIM);
    tconv_kernel<1><<<dim3(CDIM / 64, HDIM / 32, NEXP), tb, 0, sB>>>(wi, CDIM, HDIM);
    cudaEventRecord(evB, sB);
    tconv_kernel<2><<<dim3(HDIM / 64, CDIM / 32, NEXP), tb, 0, sC>>>(wo, HDIM, CDIM);
    cudaEventRecord(evC, sC);

    // routing chain on the main stream
    gate_kernel<<<NTOK / 8, 256>>>(x, w_gate);
    cnt_kernel<<<NEXP, 1024>>>();
    offs_kernel<<<1, 1>>>();
    place_kernel<<<NEXP, 1024>>>();

    // join conversions, run fused gate+up GEMM (tconv<2> overlaps with it)
    cudaStreamWaitEvent(0, evB, 0);
    moe_hmma<0><<<dim3(MT_MAX, HDIM / 128), 512, SMEM0>>>();

    cudaStreamWaitEvent(0, evC, 0);
    moe_hmma<2><<<dim3(MT_MAX, CDIM / 128), 512, SMEM2>>>();

    combine_kernel<<<NTOK * (CDIM / 4) / 256, 256>>>(out);
}

// round 14
// speedup vs baseline: 1.2529x; 1.0134x over previous
#include <cuda_runtime.h>
#include <cuda_fp16.h>
#include <cstdint>
#include <math.h>

// ---------------- problem constants ------------------------------------------
#define NTOK 8192
#define CDIM 1024
#define HDIM 2048
#define NEXP 8
#define NPAIR (NTOK * 2)
#define BM 128
#define MT_MAX 136

// ---------------- scratch ----------------------------------------------------
__device__ __half g_xh[(size_t)NTOK * CDIM];
__device__ __half g_wgT[(size_t)NEXP * HDIM * CDIM];
__device__ __half g_wiT[(size_t)NEXP * HDIM * CDIM];
__device__ __half g_woT[(size_t)NEXP * CDIM * HDIM];
__device__ __half g_h[(size_t)NPAIR * HDIM];

__device__ int   g_sel[NTOK * 2];
__device__ float g_selw[NTOK * 2];
__device__ int   g_tok[NPAIR];
__device__ float g_wt[NPAIR];
__device__ int   g_cnt[NEXP];
__device__ int   g_off[NEXP];
__device__ int   g_tileE[MT_MAX];
__device__ int   g_tileR[MT_MAX];
__device__ int   g_numTiles;

// ---------------- PTX helpers -------------------------------------------------
__device__ __forceinline__ uint32_t smem_u32(const void* p) {
    uint32_t a;
    asm("{ .reg .u64 t; cvta.to.shared.u64 t, %1; cvt.u32.u64 %0, t; }" : "=r"(a) : "l"(p));
    return a;
}
__device__ __forceinline__ void ldsm4(uint32_t* r, uint32_t addr) {
    asm volatile("ldmatrix.sync.aligned.m8n8.x4.shared.b16 {%0,%1,%2,%3}, [%4];"
                 : "=r"(r[0]), "=r"(r[1]), "=r"(r[2]), "=r"(r[3]) : "r"(addr));
}
__device__ __forceinline__ void mma_f16(float* d, const uint32_t* a, uint32_t b0, uint32_t b1) {
    asm volatile("mma.sync.aligned.m16n8k16.row.col.f32.f16.f16.f32 "
                 "{%0,%1,%2,%3}, {%4,%5,%6,%7}, {%8,%9}, {%0,%1,%2,%3};"
                 : "+f"(d[0]), "+f"(d[1]), "+f"(d[2]), "+f"(d[3])
                 : "r"(a[0]), "r"(a[1]), "r"(a[2]), "r"(a[3]), "r"(b0), "r"(b1));
}
#define CP_ASYNC16(dst, src, sz) \
    asm volatile("cp.async.cg.shared.global [%0], [%1], 16, %2;" :: "r"(dst), "l"(src), "r"(sz) : "memory")
#define CP_COMMIT() asm volatile("cp.async.commit_group;" ::: "memory")
#define CP_WAIT(n)  asm volatile("cp.async.wait_group %0;" :: "n"(n) : "memory")

// ---------------- gating (smem-cached transposed wgate) -----------------------
#define WPITCH 1028
__global__ void gate_kernel(const float* __restrict__ x, const float* __restrict__ wgate) {
    __shared__ float swT[NEXP * WPITCH];
    int tid = threadIdx.x;
    for (int i = tid; i < CDIM * NEXP; i += 256) {
        int c = i >> 3, e = i & 7;
        swT[e * WPITCH + c] = wgate[i];
    }
    __syncthreads();

    int warp = blockIdx.x * 8 + (tid >> 5);
    int lane = tid & 31;
    const float* xr = x + (size_t)warp * CDIM;

    float acc[NEXP];
#pragma unroll
    for (int e = 0; e < NEXP; e++) acc[e] = 0.f;
#pragma unroll
    for (int i = lane * 4; i < CDIM; i += 128) {
        float4 xv = *(const float4*)(xr + i);
#pragma unroll
        for (int e = 0; e < NEXP; e++) {
            float4 wv = *(const float4*)&swT[e * WPITCH + i];
            acc[e] += xv.x * wv.x + xv.y * wv.y + xv.z * wv.z + xv.w * wv.w;
        }
    }
#pragma unroll
    for (int e = 0; e < NEXP; e++)
#pragma unroll
        for (int d = 16; d > 0; d >>= 1) acc[e] += __shfl_down_sync(0xffffffffu, acc[e], d);
    if (lane == 0) {
        float m = acc[0];
#pragma unroll
        for (int e = 1; e < NEXP; e++) m = fmaxf(m, acc[e]);
        float p[NEXP]; float s = 0.f;
#pragma unroll
        for (int e = 0; e < NEXP; e++) { p[e] = expf(acc[e] - m); s += p[e]; }
        float inv = 1.f / s;
#pragma unroll
        for (int e = 0; e < NEXP; e++) p[e] *= inv;
        int i1 = 0;
#pragma unroll
        for (int e = 1; e < NEXP; e++) if (p[e] > p[i1]) i1 = e;
        int i2 = (i1 == 0) ? 1 : 0;
#pragma unroll
        for (int e = 0; e < NEXP; e++) if (e != i1 && p[e] > p[i2]) i2 = e;
        g_sel[2 * warp] = i1;     g_selw[2 * warp] = p[i1];
        g_sel[2 * warp + 1] = i2; g_selw[2 * warp + 1] = p[i2];
    }
}

// ---------------- routing: single fused kernel (count+offs+tiles+place) -------
__global__ void route_kernel() {
    __shared__ int scnt[NEXP][32];
    __shared__ int tot[NEXP];
    __shared__ int wsum[32];
    __shared__ int carry;
    int e = blockIdx.x;
    int tid = threadIdx.x, lane = tid & 31, wid = tid >> 5;

    // all-expert counts (every block computes all 8 to derive its own offset)
    int c[NEXP] = {0, 0, 0, 0, 0, 0, 0, 0};
    for (int t = tid; t < NTOK; t += 1024) {
        int s0 = g_sel[2 * t], s1 = g_sel[2 * t + 1];
#pragma unroll
        for (int k = 0; k < NEXP; k++) c[k] += (s0 == k) + (s1 == k);
    }
#pragma unroll
    for (int k = 0; k < NEXP; k++) {
#pragma unroll
        for (int d = 16; d > 0; d >>= 1) c[k] += __shfl_down_sync(0xffffffffu, c[k], d);
        if (lane == 0) scnt[k][wid] = c[k];
    }
    __syncthreads();
    if (wid < NEXP) {
        int v = scnt[wid][lane];
#pragma unroll
        for (int d = 16; d > 0; d >>= 1) v += __shfl_down_sync(0xffffffffu, v, d);
        if (lane == 0) tot[wid] = v;
    }
    __syncthreads();

    int base_off = 0;
#pragma unroll
    for (int k = 0; k < NEXP; k++) if (k < e) base_off += tot[k];
    if (tid == 0) { g_cnt[e] = tot[e]; g_off[e] = base_off; carry = 0; }
    if (e == 0 && tid == 0) {
        int nt = 0;
        for (int k = 0; k < NEXP; k++)
            for (int r = 0; r < tot[k]; r += BM) { g_tileE[nt] = k; g_tileR[nt] = r; nt++; }
        g_numTiles = nt;
    }
    __syncthreads();

    // stable placement for this block's expert
    for (int base = 0; base < NTOK; base += 1024) {
        int t = base + tid;
        int slot = (g_sel[2 * t] == e) ? 0 : ((g_sel[2 * t + 1] == e) ? 1 : -1);
        int f = (slot >= 0) ? 1 : 0;
        int v = f;
#pragma unroll
        for (int d = 1; d < 32; d <<= 1) {
            int u = __shfl_up_sync(0xffffffffu, v, d);
            if (lane >= d) v += u;
        }
        if (lane == 31) wsum[wid] = v;
        __syncthreads();
        int wbase = 0, totb = 0;
#pragma unroll
        for (int w = 0; w < 32; w++) { if (w < wid) wbase += wsum[w]; totb += wsum[w]; }
        if (f) {
            int p = base_off + carry + wbase + v - 1;
            g_tok[p] = t;
            g_wt[p] = g_selw[2 * t + slot];
        }
        __syncthreads();
        if (tid == 0) carry += totb;
        __syncthreads();
    }
}

// ---------------- x -> fp16 ----------------------------------------------------
__global__ void xconv_kernel(const float* __restrict__ x) {
    size_t i = (size_t)blockIdx.x * 512 + threadIdx.x;
    float2 v = ((const float2*)x)[i];
    ((__half2*)g_xh)[i] = __floats2half2_rn(v.x, v.y);
}

// ---------------- weight transpose + fp16 -------------------------------------
template <int W>
__global__ void tconv_kernel(const float* __restrict__ src, int K, int S) {
    __half* dst = (W == 0) ? g_wgT : (W == 1) ? g_wiT : g_woT;
    __shared__ float t[64][33];
    int e = blockIdx.z;
    int k0 = blockIdx.x * 64, s0 = blockIdx.y * 32;
    const float* sp = src + (size_t)e * K * S;
    int tx = threadIdx.x, ty = threadIdx.y;
#pragma unroll
    for (int j = 0; j < 64; j += 8)
        t[ty + j][tx] = sp[(size_t)(k0 + ty + j) * S + s0 + tx];
    __syncthreads();
    size_t dbase = (size_t)e * S * K;
#pragma unroll
    for (int j = 0; j < 32; j += 8) {
        int s = s0 + ty + j;
        __half2 h = __floats2half2_rn(t[tx * 2][ty + j], t[tx * 2 + 1][ty + j]);
        *(__half2*)&dst[dbase + (size_t)s * K + k0 + tx * 2] = h;
    }
}

// ---------------- fp16 mma GEMM, 128x128 tile, 3-stage cp.async ---------------
// MODE 0: gate/up fused -> g_h. MODE 2: y accumulated straight into out via
// atomicAdd (combine fused; out pre-zeroed by memset in the graph).
#define PITCHB 80
#define PLANEB (128 * PITCHB)
#define STAGES 3

template <int MODE>
__global__ void __launch_bounds__(512, 1)
moe_hmma(float* __restrict__ out) {
    constexpr int K = (MODE == 0) ? CDIM : HDIM;
    constexpr int KT = K / 32;
    constexpr int NW = (MODE == 0) ? 2 : 1;
    constexpr int STAGEB = (1 + NW) * PLANEB;

    extern __shared__ char smem[];
    uint32_t sb = smem_u32(smem);

    int bx = blockIdx.x;
    if (bx >= g_numTiles) return;
    int by = blockIdx.y;
    int e = g_tileE[bx], r0 = g_tileR[bx], off = g_off[e];
    int rowsLeft = g_cnt[e] - r0;
    if (rowsLeft > 128) rowsLeft = 128;
    int nb = by * 128;

    int tid = threadIdx.x, wid = tid >> 5, lane = tid & 31;
    int WM = wid & 3, WN = wid >> 2;
    int gq = lane >> 2, tg = lane & 3;

    const __half* srcB[2];
    if (MODE == 0) {
        srcB[0] = g_wgT + ((size_t)e * HDIM + nb) * CDIM;
        srcB[1] = g_wiT + ((size_t)e * HDIM + nb) * CDIM;
    } else {
        srcB[0] = g_woT + ((size_t)e * CDIM + nb) * HDIM;
    }

    int lrow = tid >> 2, lch = tid & 3;
    bool aval = lrow < rowsLeft;
    int ra = aval ? lrow : 0;
    const __half* aRowPtr;
    if (MODE == 0) {
        int tok = g_tok[off + r0 + ra];
        aRowPtr = g_xh + (size_t)tok * CDIM;
    } else {
        aRowPtr = g_h + (size_t)(off + r0 + ra) * HDIM;
    }
    uint32_t szA = aval ? 16u : 0u;

    auto load_buf = [&](int buf, int kc) {
        uint32_t base = sb + buf * STAGEB;
        int k0 = kc * 32;
        uint32_t doff = lrow * PITCHB + lch * 16;
        CP_ASYNC16(base + doff, aRowPtr + k0 + lch * 8, szA);
#pragma unroll
        for (int p = 0; p < NW; p++)
            CP_ASYNC16(base + (1 + p) * PLANEB + doff,
                       srcB[p] + (size_t)lrow * K + k0 + lch * 8, 16u);
        CP_COMMIT();
    };

    float acc[NW][2][4][4];
#pragma unroll
    for (int w = 0; w < NW; w++)
#pragma unroll
        for (int a = 0; a < 2; a++)
#pragma unroll
            for (int b = 0; b < 4; b++)
#pragma unroll
                for (int c = 0; c < 4; c++) acc[w][a][b][c] = 0.f;

    load_buf(0, 0);
    load_buf(1, 1);

    uint32_t aRowOff = (WM * 32 + (lane & 15)) * PITCHB + (lane >> 4) * 16;
    uint32_t bRowOff = (WN * 32 + (lane & 15)) * PITCHB + (lane >> 4) * 16;

    int cb = 0;
    for (int kc = 0; kc < KT; kc++) {
        if (kc + 1 < KT) { CP_WAIT(1); } else { CP_WAIT(0); }
        __syncthreads();
        if (kc + 2 < KT) {
            int lb = cb + 2; if (lb >= STAGES) lb -= STAGES;
            load_buf(lb, kc + 2);
        }

        uint32_t base = sb + cb * STAGEB;
#pragma unroll
        for (int ks = 0; ks < 2; ks++) {
            uint32_t kOff = ks * 32;
            uint32_t a[2][4];
#pragma unroll
            for (int mi = 0; mi < 2; mi++)
                ldsm4(a[mi], base + aRowOff + mi * 16 * PITCHB + kOff);
#pragma unroll
            for (int w = 0; w < NW; w++) {
                uint32_t b[2][4];
                uint32_t bBase = base + (1 + w) * PLANEB;
#pragma unroll
                for (int ng = 0; ng < 2; ng++)
                    ldsm4(b[ng], bBase + bRowOff + ng * 16 * PITCHB + kOff);
#pragma unroll
                for (int mi = 0; mi < 2; mi++)
#pragma unroll
                    for (int nj = 0; nj < 4; nj++) {
                        int ng = nj >> 1, ix = nj & 1;
                        mma_f16(acc[w][mi][nj], a[mi], b[ng][ix], b[ng][ix + 2]);
                    }
            }
        }
        cb++; if (cb >= STAGES) cb = 0;
        __syncthreads();
    }

    // ---- epilogue ----
    int grb = off + r0;
#pragma unroll
    for (int mi = 0; mi < 2; mi++) {
#pragma unroll
        for (int half = 0; half < 2; half++) {
            int r = WM * 32 + mi * 16 + gq + half * 8;
            if (r >= rowsLeft) continue;
            size_t grow = (size_t)(grb + r);
            int tok = 0; float wcomb = 0.f;
            if (MODE == 2) { tok = g_tok[grow]; wcomb = g_wt[grow]; }
#pragma unroll
            for (int nj = 0; nj < 4; nj++) {
                int c = nb + WN * 32 + nj * 8 + tg * 2;
                if (MODE == 0) {
                    float gt0 = acc[0][mi][nj][half * 2 + 0];
                    float gt1 = acc[0][mi][nj][half * 2 + 1];
                    float up0 = acc[1][mi][nj][half * 2 + 0];
                    float up1 = acc[1][mi][nj][half * 2 + 1];
                    float h0 = up0 * gt0 / (1.f + __expf(-gt0));
                    float h1 = up1 * gt1 / (1.f + __expf(-gt1));
                    __half ph0 = __float2half_rn(h0);
                    __half ph1 = __float2half_rn(h1);
                    uint32_t pk = ((uint32_t)__half_as_ushort(ph1) << 16) | __half_as_ushort(ph0);
                    *(uint32_t*)&g_h[grow * HDIM + c] = pk;
                } else {
                    float d0 = acc[0][mi][nj][half * 2 + 0];
                    float d1 = acc[0][mi][nj][half * 2 + 1];
                    float* orow = out + (size_t)tok * CDIM + c;
                    atomicAdd(orow, wcomb * d0);
                    atomicAdd(orow + 1, wcomb * d1);
                }
            }
        }
    }
}

// ---------------- launch (stream-forked graph) --------------------------------
#define SMEM0 (STAGES * 3 * PLANEB)   // 92160
#define SMEM2 (STAGES * 2 * PLANEB)   // 61440

extern "C" void kernel_launch(void* const* d_in, const int* in_sizes, int n_in,
                              void* d_out, int out_size) {
    const float* x      = (const float*)d_in[0];
    const float* w_gate = (const float*)d_in[1];
    const float* wi     = (const float*)d_in[2];
    const float* wg     = (const float*)d_in[3];
    const float* wo     = (const float*)d_in[4];
    float* out = (float*)d_out;

    static cudaStream_t sB = nullptr, sC = nullptr;
    static cudaEvent_t evFork = nullptr, evB = nullptr, evC = nullptr;
    if (sB == nullptr) {
        cudaStreamCreateWithFlags(&sB, cudaStreamNonBlocking);
        cudaStreamCreateWithFlags(&sC, cudaStreamNonBlocking);
        cudaEventCreateWithFlags(&evFork, cudaEventDisableTiming);
        cudaEventCreateWithFlags(&evB, cudaEventDisableTiming);
        cudaEventCreateWithFlags(&evC, cudaEventDisableTiming);
        cudaFuncSetAttribute(moe_hmma<0>, cudaFuncAttributeMaxDynamicSharedMemorySize, SMEM0);
        cudaFuncSetAttribute(moe_hmma<2>, cudaFuncAttributeMaxDynamicSharedMemorySize, SMEM2);
    }

    // fork: conversions + output zeroing run concurrently with routing chain
    cudaEventRecord(evFork, 0);
    cudaStreamWaitEvent(sB, evFork, 0);
    cudaStreamWaitEvent(sC, evFork, 0);

    dim3 tb(32, 8);
    xconv_kernel<<<NTOK * CDIM / 1024, 512, 0, sB>>>(x);
    tconv_kernel<0><<<dim3(CDIM / 64, HDIM / 32, NEXP), tb, 0, sB>>>(wg, CDIM, HDIM);
    tconv_kernel<1><<<dim3(CDIM / 64, HDIM / 32, NEXP), tb, 0, sB>>>(wi, CDIM, HDIM);
    cudaEventRecord(evB, sB);
    cudaMemsetAsync(out, 0, (size_t)out_size * sizeof(float), sC);
    tconv_kernel<2><<<dim3(HDIM / 64, CDIM / 32, NEXP), tb, 0, sC>>>(wo, HDIM, CDIM);
    cudaEventRecord(evC, sC);

    // routing chain on the main stream
    gate_kernel<<<NTOK / 8, 256>>>(x, w_gate);
    route_kernel<<<NEXP, 1024>>>();

    // join conversions, run fused gate+up GEMM (stream C overlaps with it)
    cudaStreamWaitEvent(0, evB, 0);
    moe_hmma<0><<<dim3(MT_MAX, HDIM / 128), 512, SMEM0>>>(nullptr);

    // join wo conversion + out zeroing, run down GEMM with fused combine
    cudaStreamWaitEvent(0, evC, 0);
    moe_hmma<2><<<dim3(MT_MAX, CDIM / 128), 512, SMEM2>>>(out);
}

// round 15
// speedup vs baseline: 1.2793x; 1.0211x over previous
#include <cuda_runtime.h>
#include <cuda_fp16.h>
#include <cstdint>
#include <math.h>

// ---------------- problem constants ------------------------------------------
#define NTOK 8192
#define CDIM 1024
#define HDIM 2048
#define NEXP 8
#define NPAIR (NTOK * 2)
#define BM 128
#define MT_MAX 136

// ---------------- scratch ----------------------------------------------------
__device__ __half g_xh[(size_t)NTOK * CDIM];
__device__ __half g_wgT[(size_t)NEXP * HDIM * CDIM];
__device__ __half g_wiT[(size_t)NEXP * HDIM * CDIM];
__device__ __half g_woT[(size_t)NEXP * CDIM * HDIM];
__device__ __half g_h[(size_t)NPAIR * HDIM];

__device__ int   g_sel[NTOK * 2];
__device__ float g_selw[NTOK * 2];
__device__ int   g_tok[NPAIR];
__device__ float g_wt[NPAIR];
__device__ int   g_cnt[NEXP];
__device__ int   g_off[NEXP];
__device__ int   g_tileE[MT_MAX];
__device__ int   g_tileR[MT_MAX];
__device__ int   g_numTiles;

// ---------------- PTX helpers -------------------------------------------------
__device__ __forceinline__ uint32_t smem_u32(const void* p) {
    uint32_t a;
    asm("{ .reg .u64 t; cvta.to.shared.u64 t, %1; cvt.u32.u64 %0, t; }" : "=r"(a) : "l"(p));
    return a;
}
__device__ __forceinline__ void ldsm4(uint32_t* r, uint32_t addr) {
    asm volatile("ldmatrix.sync.aligned.m8n8.x4.shared.b16 {%0,%1,%2,%3}, [%4];"
                 : "=r"(r[0]), "=r"(r[1]), "=r"(r[2]), "=r"(r[3]) : "r"(addr));
}
__device__ __forceinline__ void mma_f16(float* d, const uint32_t* a, uint32_t b0, uint32_t b1) {
    asm volatile("mma.sync.aligned.m16n8k16.row.col.f32.f16.f16.f32 "
                 "{%0,%1,%2,%3}, {%4,%5,%6,%7}, {%8,%9}, {%0,%1,%2,%3};"
                 : "+f"(d[0]), "+f"(d[1]), "+f"(d[2]), "+f"(d[3])
                 : "r"(a[0]), "r"(a[1]), "r"(a[2]), "r"(a[3]), "r"(b0), "r"(b1));
}
#define CP_ASYNC16(dst, src, sz) \
    asm volatile("cp.async.cg.shared.global [%0], [%1], 16, %2;" :: "r"(dst), "l"(src), "r"(sz) : "memory")
#define CP_COMMIT() asm volatile("cp.async.commit_group;" ::: "memory")
#define CP_WAIT(n)  asm volatile("cp.async.wait_group %0;" :: "n"(n) : "memory")

// ---------------- gating (512 thr, 16 tokens/block, smem wgate^T) -------------
#define WPITCH 1028
__global__ void gate_kernel(const float* __restrict__ x, const float* __restrict__ wgate) {
    __shared__ float swT[NEXP * WPITCH];
    int tid = threadIdx.x;
    for (int i = tid; i < CDIM * NEXP; i += 512) {
        int c = i >> 3, e = i & 7;
        swT[e * WPITCH + c] = wgate[i];
    }
    __syncthreads();

    int warp = blockIdx.x * 16 + (tid >> 5);
    int lane = tid & 31;
    const float* xr = x + (size_t)warp * CDIM;

    float acc[NEXP];
#pragma unroll
    for (int e = 0; e < NEXP; e++) acc[e] = 0.f;
#pragma unroll
    for (int i = lane * 4; i < CDIM; i += 128) {
        float4 xv = *(const float4*)(xr + i);
#pragma unroll
        for (int e = 0; e < NEXP; e++) {
            float4 wv = *(const float4*)&swT[e * WPITCH + i];
            acc[e] += xv.x * wv.x + xv.y * wv.y + xv.z * wv.z + xv.w * wv.w;
        }
    }
#pragma unroll
    for (int e = 0; e < NEXP; e++)
#pragma unroll
        for (int d = 16; d > 0; d >>= 1) acc[e] += __shfl_down_sync(0xffffffffu, acc[e], d);
    if (lane == 0) {
        float m = acc[0];
#pragma unroll
        for (int e = 1; e < NEXP; e++) m = fmaxf(m, acc[e]);
        float p[NEXP]; float s = 0.f;
#pragma unroll
        for (int e = 0; e < NEXP; e++) { p[e] = expf(acc[e] - m); s += p[e]; }
        float inv = 1.f / s;
#pragma unroll
        for (int e = 0; e < NEXP; e++) p[e] *= inv;
        int i1 = 0;
#pragma unroll
        for (int e = 1; e < NEXP; e++) if (p[e] > p[i1]) i1 = e;
        int i2 = (i1 == 0) ? 1 : 0;
#pragma unroll
        for (int e = 0; e < NEXP; e++) if (e != i1 && p[e] > p[i2]) i2 = e;
        g_sel[2 * warp] = i1;     g_selw[2 * warp] = p[i1];
        g_sel[2 * warp + 1] = i2; g_selw[2 * warp + 1] = p[i2];
    }
}

// ---------------- routing: single fused kernel --------------------------------
__global__ void route_kernel() {
    __shared__ int scnt[NEXP][32];
    __shared__ int tot[NEXP];
    __shared__ int wsum[32];
    __shared__ int carry;
    int e = blockIdx.x;
    int tid = threadIdx.x, lane = tid & 31, wid = tid >> 5;

    int c[NEXP] = {0, 0, 0, 0, 0, 0, 0, 0};
    for (int t = tid; t < NTOK; t += 1024) {
        int s0 = g_sel[2 * t], s1 = g_sel[2 * t + 1];
#pragma unroll
        for (int k = 0; k < NEXP; k++) c[k] += (s0 == k) + (s1 == k);
    }
#pragma unroll
    for (int k = 0; k < NEXP; k++) {
#pragma unroll
        for (int d = 16; d > 0; d >>= 1) c[k] += __shfl_down_sync(0xffffffffu, c[k], d);
        if (lane == 0) scnt[k][wid] = c[k];
    }
    __syncthreads();
    if (wid < NEXP) {
        int v = scnt[wid][lane];
#pragma unroll
        for (int d = 16; d > 0; d >>= 1) v += __shfl_down_sync(0xffffffffu, v, d);
        if (lane == 0) tot[wid] = v;
    }
    __syncthreads();

    int base_off = 0;
#pragma unroll
    for (int k = 0; k < NEXP; k++) if (k < e) base_off += tot[k];
    if (tid == 0) { g_cnt[e] = tot[e]; g_off[e] = base_off; carry = 0; }
    if (e == 0 && tid == 0) {
        int nt = 0;
        for (int k = 0; k < NEXP; k++)
            for (int r = 0; r < tot[k]; r += BM) { g_tileE[nt] = k; g_tileR[nt] = r; nt++; }
        g_numTiles = nt;
    }
    __syncthreads();

    for (int base = 0; base < NTOK; base += 1024) {
        int t = base + tid;
        int slot = (g_sel[2 * t] == e) ? 0 : ((g_sel[2 * t + 1] == e) ? 1 : -1);
        int f = (slot >= 0) ? 1 : 0;
        int v = f;
#pragma unroll
        for (int d = 1; d < 32; d <<= 1) {
            int u = __shfl_up_sync(0xffffffffu, v, d);
            if (lane >= d) v += u;
        }
        if (lane == 31) wsum[wid] = v;
        __syncthreads();
        int wbase = 0, totb = 0;
#pragma unroll
        for (int w = 0; w < 32; w++) { if (w < wid) wbase += wsum[w]; totb += wsum[w]; }
        if (f) {
            int p = base_off + carry + wbase + v - 1;
            g_tok[p] = t;
            g_wt[p] = g_selw[2 * t + slot];
        }
        __syncthreads();
        if (tid == 0) carry += totb;
        __syncthreads();
    }
}

// ---------------- x -> fp16 ----------------------------------------------------
__global__ void xconv_kernel(const float* __restrict__ x) {
    size_t i = (size_t)blockIdx.x * 512 + threadIdx.x;
    float2 v = ((const float2*)x)[i];
    ((__half2*)g_xh)[i] = __floats2half2_rn(v.x, v.y);
}

// ---------------- weight transpose + fp16 -------------------------------------
template <int W>
__global__ void tconv_kernel(const float* __restrict__ src, int K, int S) {
    __half* dst = (W == 0) ? g_wgT : (W == 1) ? g_wiT : g_woT;
    __shared__ float t[64][33];
    int e = blockIdx.z;
    int k0 = blockIdx.x * 64, s0 = blockIdx.y * 32;
    const float* sp = src + (size_t)e * K * S;
    int tx = threadIdx.x, ty = threadIdx.y;
#pragma unroll
    for (int j = 0; j < 64; j += 8)
        t[ty + j][tx] = sp[(size_t)(k0 + ty + j) * S + s0 + tx];
    __syncthreads();
    size_t dbase = (size_t)e * S * K;
#pragma unroll
    for (int j = 0; j < 32; j += 8) {
        int s = s0 + ty + j;
        __half2 h = __floats2half2_rn(t[tx * 2][ty + j], t[tx * 2 + 1][ty + j]);
        *(__half2*)&dst[dbase + (size_t)s * K + k0 + tx * 2] = h;
    }
}

// ---------------- fp16 mma GEMM, 128x128 tile, 4-stage cp.async ---------------
// MODE 0: gate/up fused -> g_h. MODE 2: y -> atomicAdd into out (pre-zeroed).
#define PITCHB 80
#define PLANEB (128 * PITCHB)
#define STAGES 4

template <int MODE>
__global__ void __launch_bounds__(512, 1)
moe_hmma(float* __restrict__ out) {
    constexpr int K = (MODE == 0) ? CDIM : HDIM;
    constexpr int KT = K / 32;
    constexpr int NW = (MODE == 0) ? 2 : 1;
    constexpr int STAGEB = (1 + NW) * PLANEB;

    extern __shared__ char smem[];
    uint32_t sb = smem_u32(smem);

    int bx = blockIdx.x;
    if (bx >= g_numTiles) return;
    int by = blockIdx.y;
    int e = g_tileE[bx], r0 = g_tileR[bx], off = g_off[e];
    int rowsLeft = g_cnt[e] - r0;
    if (rowsLeft > 128) rowsLeft = 128;
    int nb = by * 128;

    int tid = threadIdx.x, wid = tid >> 5, lane = tid & 31;
    int WM = wid & 3, WN = wid >> 2;
    int gq = lane >> 2, tg = lane & 3;

    const __half* srcB[2];
    if (MODE == 0) {
        srcB[0] = g_wgT + ((size_t)e * HDIM + nb) * CDIM;
        srcB[1] = g_wiT + ((size_t)e * HDIM + nb) * CDIM;
    } else {
        srcB[0] = g_woT + ((size_t)e * CDIM + nb) * HDIM;
    }

    int lrow = tid >> 2, lch = tid & 3;
    bool aval = lrow < rowsLeft;
    int ra = aval ? lrow : 0;
    const __half* aRowPtr;
    if (MODE == 0) {
        int tok = g_tok[off + r0 + ra];
        aRowPtr = g_xh + (size_t)tok * CDIM;
    } else {
        aRowPtr = g_h + (size_t)(off + r0 + ra) * HDIM;
    }
    uint32_t szA = aval ? 16u : 0u;

    auto load_buf = [&](int buf, int kc) {
        uint32_t base = sb + buf * STAGEB;
        int k0 = kc * 32;
        uint32_t doff = lrow * PITCHB + lch * 16;
        CP_ASYNC16(base + doff, aRowPtr + k0 + lch * 8, szA);
#pragma unroll
        for (int p = 0; p < NW; p++)
            CP_ASYNC16(base + (1 + p) * PLANEB + doff,
                       srcB[p] + (size_t)lrow * K + k0 + lch * 8, 16u);
        CP_COMMIT();
    };

    float acc[NW][2][4][4];
#pragma unroll
    for (int w = 0; w < NW; w++)
#pragma unroll
        for (int a = 0; a < 2; a++)
#pragma unroll
            for (int b = 0; b < 4; b++)
#pragma unroll
                for (int c = 0; c < 4; c++) acc[w][a][b][c] = 0.f;

    // prologue: 3 chunks in flight
    load_buf(0, 0);
    load_buf(1, 1);
    load_buf(2, 2);

    uint32_t aRowOff = (WM * 32 + (lane & 15)) * PITCHB + (lane >> 4) * 16;
    uint32_t bRowOff = (WN * 32 + (lane & 15)) * PITCHB + (lane >> 4) * 16;

    int cb = 0;
    for (int kc = 0; kc < KT; kc++) {
        int inflight = KT - 1 - kc;     // groups still pending after this one
        if (inflight >= 2)      { CP_WAIT(2); }
        else if (inflight == 1) { CP_WAIT(1); }
        else                    { CP_WAIT(0); }
        __syncthreads();
        if (kc + 3 < KT) {
            int lb = cb + 3; if (lb >= STAGES) lb -= STAGES;
            load_buf(lb, kc + 3);
        }

        uint32_t base = sb + cb * STAGEB;
#pragma unroll
        for (int ks = 0; ks < 2; ks++) {
            uint32_t kOff = ks * 32;
            uint32_t a[2][4];
#pragma unroll
            for (int mi = 0; mi < 2; mi++)
                ldsm4(a[mi], base + aRowOff + mi * 16 * PITCHB + kOff);
#pragma unroll
            for (int w = 0; w < NW; w++) {
                uint32_t b[2][4];
                uint32_t bBase = base + (1 + w) * PLANEB;
#pragma unroll
                for (int ng = 0; ng < 2; ng++)
                    ldsm4(b[ng], bBase + bRowOff + ng * 16 * PITCHB + kOff);
#pragma unroll
                for (int mi = 0; mi < 2; mi++)
#pragma unroll
                    for (int nj = 0; nj < 4; nj++) {
                        int ng = nj >> 1, ix = nj & 1;
                        mma_f16(acc[w][mi][nj], a[mi], b[ng][ix], b[ng][ix + 2]);
                    }
            }
        }
        cb++; if (cb >= STAGES) cb = 0;
        __syncthreads();
    }

    // ---- epilogue ----
    int grb = off + r0;
#pragma unroll
    for (int mi = 0; mi < 2; mi++) {
#pragma unroll
        for (int half = 0; half < 2; half++) {
            int r = WM * 32 + mi * 16 + gq + half * 8;
            if (r >= rowsLeft) continue;
            size_t grow = (size_t)(grb + r);
            int tok = 0; float wcomb = 0.f;
            if (MODE == 2) { tok = g_tok[grow]; wcomb = g_wt[grow]; }
#pragma unroll
            for (int nj = 0; nj < 4; nj++) {
                int c = nb + WN * 32 + nj * 8 + tg * 2;
                if (MODE == 0) {
                    float gt0 = acc[0][mi][nj][half * 2 + 0];
                    float gt1 = acc[0][mi][nj][half * 2 + 1];
                    float up0 = acc[1][mi][nj][half * 2 + 0];
                    float up1 = acc[1][mi][nj][half * 2 + 1];
                    float h0 = up0 * gt0 / (1.f + __expf(-gt0));
                    float h1 = up1 * gt1 / (1.f + __expf(-gt1));
                    __half ph0 = __float2half_rn(h0);
                    __half ph1 = __float2half_rn(h1);
                    uint32_t pk = ((uint32_t)__half_as_ushort(ph1) << 16) | __half_as_ushort(ph0);
                    *(uint32_t*)&g_h[grow * HDIM + c] = pk;
                } else {
                    float d0 = acc[0][mi][nj][half * 2 + 0];
                    float d1 = acc[0][mi][nj][half * 2 + 1];
                    float* orow = out + (size_t)tok * CDIM + c;
                    atomicAdd(orow, wcomb * d0);
                    atomicAdd(orow + 1, wcomb * d1);
                }
            }
        }
    }
}

// ---------------- launch (stream-forked graph) --------------------------------
#define SMEM0 (STAGES * 3 * PLANEB)   // 122880
#define SMEM2 (STAGES * 2 * PLANEB)   // 81920

extern "C" void kernel_launch(void* const* d_in, const int* in_sizes, int n_in,
                              void* d_out, int out_size) {
    const float* x      = (const float*)d_in[0];
    const float* w_gate = (const float*)d_in[1];
    const float* wi     = (const float*)d_in[2];
    const float* wg     = (const float*)d_in[3];
    const float* wo     = (const float*)d_in[4];
    float* out = (float*)d_out;

    static cudaStream_t sB = nullptr, sC = nullptr;
    static cudaEvent_t evFork = nullptr, evB = nullptr, evC = nullptr;
    if (sB == nullptr) {
        cudaStreamCreateWithFlags(&sB, cudaStreamNonBlocking);
        cudaStreamCreateWithFlags(&sC, cudaStreamNonBlocking);
        cudaEventCreateWithFlags(&evFork, cudaEventDisableTiming);
        cudaEventCreateWithFlags(&evB, cudaEventDisableTiming);
        cudaEventCreateWithFlags(&evC, cudaEventDisableTiming);
        cudaFuncSetAttribute(moe_hmma<0>, cudaFuncAttributeMaxDynamicSharedMemorySize, SMEM0);
        cudaFuncSetAttribute(moe_hmma<2>, cudaFuncAttributeMaxDynamicSharedMemorySize, SMEM2);
    }

    // fork: conversions + output zeroing run concurrently with routing chain
    cudaEventRecord(evFork, 0);
    cudaStreamWaitEvent(sB, evFork, 0);
    cudaStreamWaitEvent(sC, evFork, 0);

    dim3 tb(32, 8);
    xconv_kernel<<<NTOK * CDIM / 1024, 512, 0, sB>>>(x);
    tconv_kernel<0><<<dim3(CDIM / 64, HDIM / 32, NEXP), tb, 0, sB>>>(wg, CDIM, HDIM);
    tconv_kernel<1><<<dim3(CDIM / 64, HDIM / 32, NEXP), tb, 0, sB>>>(wi, CDIM, HDIM);
    cudaEventRecord(evB, sB);
    cudaMemsetAsync(out, 0, (size_t)out_size * sizeof(float), sC);
    tconv_kernel<2><<<dim3(HDIM / 64, CDIM / 32, NEXP), tb, 0, sC>>>(wo, HDIM, CDIM);
    cudaEventRecord(evC, sC);

    // routing chain on the main stream
    gate_kernel<<<NTOK / 16, 512>>>(x, w_gate);
    route_kernel<<<NEXP, 1024>>>();

    // join conversions, run fused gate+up GEMM
    cudaStreamWaitEvent(0, evB, 0);
    moe_hmma<0><<<dim3(MT_MAX, HDIM / 128), 512, SMEM0>>>(nullptr);

    // join wo conversion + out zeroing, run down GEMM with fused combine
    cudaStreamWaitEvent(0, evC, 0);
    moe_hmma<2><<<dim3(MT_MAX, CDIM / 128), 512, SMEM2>>>(out);
}

// round 16
// speedup vs baseline: 1.3190x; 1.0311x over previous
#include <cuda_runtime.h>
#include <cuda_fp16.h>
#include <cstdint>
#include <math.h>

// ---------------- problem constants ------------------------------------------
#define NTOK 8192
#define CDIM 1024
#define HDIM 2048
#define NEXP 8
#define NPAIR (NTOK * 2)
#define BM 128
#define MT_MAX 136

// ---------------- scratch ----------------------------------------------------
__device__ __half g_xh[(size_t)NTOK * CDIM];
__device__ __half g_wgT[(size_t)NEXP * HDIM * CDIM];
__device__ __half g_wiT[(size_t)NEXP * HDIM * CDIM];
__device__ __half g_woT[(size_t)NEXP * CDIM * HDIM];
__device__ __half g_h[(size_t)NPAIR * HDIM];

__device__ int   g_sel[NTOK * 2];
__device__ float g_selw[NTOK * 2];
__device__ int   g_tok[NPAIR];
__device__ float g_wt[NPAIR];
__device__ int   g_cnt[NEXP];
__device__ int   g_off[NEXP];
__device__ int   g_tileE[MT_MAX];
__device__ int   g_tileR[MT_MAX];
__device__ int   g_numTiles;

// ---------------- PTX helpers -------------------------------------------------
__device__ __forceinline__ uint32_t smem_u32(const void* p) {
    uint32_t a;
    asm("{ .reg .u64 t; cvta.to.shared.u64 t, %1; cvt.u32.u64 %0, t; }" : "=r"(a) : "l"(p));
    return a;
}
__device__ __forceinline__ void ldsm4(uint32_t* r, uint32_t addr) {
    asm volatile("ldmatrix.sync.aligned.m8n8.x4.shared.b16 {%0,%1,%2,%3}, [%4];"
                 : "=r"(r[0]), "=r"(r[1]), "=r"(r[2]), "=r"(r[3]) : "r"(addr));
}
__device__ __forceinline__ void mma_f16(float* d, const uint32_t* a, uint32_t b0, uint32_t b1) {
    asm volatile("mma.sync.aligned.m16n8k16.row.col.f32.f16.f16.f32 "
                 "{%0,%1,%2,%3}, {%4,%5,%6,%7}, {%8,%9}, {%0,%1,%2,%3};"
                 : "+f"(d[0]), "+f"(d[1]), "+f"(d[2]), "+f"(d[3])
                 : "r"(a[0]), "r"(a[1]), "r"(a[2]), "r"(a[3]), "r"(b0), "r"(b1));
}
#define CP_ASYNC16(dst, src, sz) \
    asm volatile("cp.async.cg.shared.global [%0], [%1], 16, %2;" :: "r"(dst), "l"(src), "r"(sz) : "memory")
#define CP_COMMIT() asm volatile("cp.async.commit_group;" ::: "memory")
#define CP_WAIT(n)  asm volatile("cp.async.wait_group %0;" :: "n"(n) : "memory")

// ---------------- gating (512 thr, 16 tokens/block, smem wgate^T) -------------
#define WPITCH 1028
__global__ void gate_kernel(const float* __restrict__ x, const float* __restrict__ wgate) {
    __shared__ float swT[NEXP * WPITCH];
    int tid = threadIdx.x;
    for (int i = tid; i < CDIM * NEXP; i += 512) {
        int c = i >> 3, e = i & 7;
        swT[e * WPITCH + c] = wgate[i];
    }
    __syncthreads();

    int warp = blockIdx.x * 16 + (tid >> 5);
    int lane = tid & 31;
    const float* xr = x + (size_t)warp * CDIM;

    float acc[NEXP];
#pragma unroll
    for (int e = 0; e < NEXP; e++) acc[e] = 0.f;
#pragma unroll
    for (int i = lane * 4; i < CDIM; i += 128) {
        float4 xv = *(const float4*)(xr + i);
#pragma unroll
        for (int e = 0; e < NEXP; e++) {
            float4 wv = *(const float4*)&swT[e * WPITCH + i];
            acc[e] += xv.x * wv.x + xv.y * wv.y + xv.z * wv.z + xv.w * wv.w;
        }
    }
#pragma unroll
    for (int e = 0; e < NEXP; e++)
#pragma unroll
        for (int d = 16; d > 0; d >>= 1) acc[e] += __shfl_down_sync(0xffffffffu, acc[e], d);
    if (lane == 0) {
        float m = acc[0];
#pragma unroll
        for (int e = 1; e < NEXP; e++) m = fmaxf(m, acc[e]);
        float p[NEXP]; float s = 0.f;
#pragma unroll
        for (int e = 0; e < NEXP; e++) { p[e] = expf(acc[e] - m); s += p[e]; }
        float inv = 1.f / s;
#pragma unroll
        for (int e = 0; e < NEXP; e++) p[e] *= inv;
        int i1 = 0;
#pragma unroll
        for (int e = 1; e < NEXP; e++) if (p[e] > p[i1]) i1 = e;
        int i2 = (i1 == 0) ? 1 : 0;
#pragma unroll
        for (int e = 0; e < NEXP; e++) if (e != i1 && p[e] > p[i2]) i2 = e;
        g_sel[2 * warp] = i1;     g_selw[2 * warp] = p[i1];
        g_sel[2 * warp + 1] = i2; g_selw[2 * warp + 1] = p[i2];
    }
}

// ---------------- routing: single fused kernel --------------------------------
__global__ void route_kernel() {
    __shared__ int scnt[NEXP][32];
    __shared__ int tot[NEXP];
    __shared__ int wsum[32];
    __shared__ int carry;
    int e = blockIdx.x;
    int tid = threadIdx.x, lane = tid & 31, wid = tid >> 5;

    int c[NEXP] = {0, 0, 0, 0, 0, 0, 0, 0};
    for (int t = tid; t < NTOK; t += 1024) {
        int s0 = g_sel[2 * t], s1 = g_sel[2 * t + 1];
#pragma unroll
        for (int k = 0; k < NEXP; k++) c[k] += (s0 == k) + (s1 == k);
    }
#pragma unroll
    for (int k = 0; k < NEXP; k++) {
#pragma unroll
        for (int d = 16; d > 0; d >>= 1) c[k] += __shfl_down_sync(0xffffffffu, c[k], d);
        if (lane == 0) scnt[k][wid] = c[k];
    }
    __syncthreads();
    if (wid < NEXP) {
        int v = scnt[wid][lane];
#pragma unroll
        for (int d = 16; d > 0; d >>= 1) v += __shfl_down_sync(0xffffffffu, v, d);
        if (lane == 0) tot[wid] = v;
    }
    __syncthreads();

    int base_off = 0;
#pragma unroll
    for (int k = 0; k < NEXP; k++) if (k < e) base_off += tot[k];
    if (tid == 0) { g_cnt[e] = tot[e]; g_off[e] = base_off; carry = 0; }
    if (e == 0 && tid == 0) {
        int nt = 0;
        for (int k = 0; k < NEXP; k++)
            for (int r = 0; r < tot[k]; r += BM) { g_tileE[nt] = k; g_tileR[nt] = r; nt++; }
        g_numTiles = nt;
    }
    __syncthreads();

    for (int base = 0; base < NTOK; base += 1024) {
        int t = base + tid;
        int slot = (g_sel[2 * t] == e) ? 0 : ((g_sel[2 * t + 1] == e) ? 1 : -1);
        int f = (slot >= 0) ? 1 : 0;
        int v = f;
#pragma unroll
        for (int d = 1; d < 32; d <<= 1) {
            int u = __shfl_up_sync(0xffffffffu, v, d);
            if (lane >= d) v += u;
        }
        if (lane == 31) wsum[wid] = v;
        __syncthreads();
        int wbase = 0, totb = 0;
#pragma unroll
        for (int w = 0; w < 32; w++) { if (w < wid) wbase += wsum[w]; totb += wsum[w]; }
        if (f) {
            int p = base_off + carry + wbase + v - 1;
            g_tok[p] = t;
            g_wt[p] = g_selw[2 * t + slot];
        }
        __syncthreads();
        if (tid == 0) carry += totb;
        __syncthreads();
    }
}

// ---------------- x -> fp16 ----------------------------------------------------
__global__ void xconv_kernel(const float* __restrict__ x) {
    size_t i = (size_t)blockIdx.x * 512 + threadIdx.x;
    float2 v = ((const float2*)x)[i];
    ((__half2*)g_xh)[i] = __floats2half2_rn(v.x, v.y);
}

// ---------------- weight transpose + fp16 -------------------------------------
template <int W>
__global__ void tconv_kernel(const float* __restrict__ src, int K, int S) {
    __half* dst = (W == 0) ? g_wgT : (W == 1) ? g_wiT : g_woT;
    __shared__ float t[64][33];
    int e = blockIdx.z;
    int k0 = blockIdx.x * 64, s0 = blockIdx.y * 32;
    const float* sp = src + (size_t)e * K * S;
    int tx = threadIdx.x, ty = threadIdx.y;
#pragma unroll
    for (int j = 0; j < 64; j += 8)
        t[ty + j][tx] = sp[(size_t)(k0 + ty + j) * S + s0 + tx];
    __syncthreads();
    size_t dbase = (size_t)e * S * K;
#pragma unroll
    for (int j = 0; j < 32; j += 8) {
        int s = s0 + ty + j;
        __half2 h = __floats2half2_rn(t[tx * 2][ty + j], t[tx * 2 + 1][ty + j]);
        *(__half2*)&dst[dbase + (size_t)s * K + k0 + tx * 2] = h;
    }
}

// ---------------- fp16 mma GEMM, 128x128 tile, 4-stage cp.async ---------------
// MODE 0: gate/up fused -> g_h. MODE 2: y -> atomicAdd into out (pre-zeroed).
// One barrier per chunk: loads are issued AFTER the leading wait+sync, so the
// iteration-j barrier already separates COMPUTE(j-1) from the overwrite of
// buffer (j-1)%4 by LOAD(j+3) — the trailing barrier was redundant.
#define PITCHB 80
#define PLANEB (128 * PITCHB)
#define STAGES 4

template <int MODE>
__global__ void __launch_bounds__(512, 1)
moe_hmma(float* __restrict__ out) {
    constexpr int K = (MODE == 0) ? CDIM : HDIM;
    constexpr int KT = K / 32;
    constexpr int NW = (MODE == 0) ? 2 : 1;
    constexpr int STAGEB = (1 + NW) * PLANEB;

    extern __shared__ char smem[];
    uint32_t sb = smem_u32(smem);

    int bx = blockIdx.x;
    if (bx >= g_numTiles) return;
    int by = blockIdx.y;
    int e = g_tileE[bx], r0 = g_tileR[bx], off = g_off[e];
    int rowsLeft = g_cnt[e] - r0;
    if (rowsLeft > 128) rowsLeft = 128;
    int nb = by * 128;

    int tid = threadIdx.x, wid = tid >> 5, lane = tid & 31;
    int WM = wid & 3, WN = wid >> 2;
    int gq = lane >> 2, tg = lane & 3;

    const __half* srcB[2];
    if (MODE == 0) {
        srcB[0] = g_wgT + ((size_t)e * HDIM + nb) * CDIM;
        srcB[1] = g_wiT + ((size_t)e * HDIM + nb) * CDIM;
    } else {
        srcB[0] = g_woT + ((size_t)e * CDIM + nb) * HDIM;
    }

    int lrow = tid >> 2, lch = tid & 3;
    bool aval = lrow < rowsLeft;
    int ra = aval ? lrow : 0;
    const __half* aRowPtr;
    if (MODE == 0) {
        int tok = g_tok[off + r0 + ra];
        aRowPtr = g_xh + (size_t)tok * CDIM;
    } else {
        aRowPtr = g_h + (size_t)(off + r0 + ra) * HDIM;
    }
    uint32_t szA = aval ? 16u : 0u;

    auto load_buf = [&](int buf, int kc) {
        uint32_t base = sb + buf * STAGEB;
        int k0 = kc * 32;
        uint32_t doff = lrow * PITCHB + lch * 16;
        CP_ASYNC16(base + doff, aRowPtr + k0 + lch * 8, szA);
#pragma unroll
        for (int p = 0; p < NW; p++)
            CP_ASYNC16(base + (1 + p) * PLANEB + doff,
                       srcB[p] + (size_t)lrow * K + k0 + lch * 8, 16u);
        CP_COMMIT();
    };

    float acc[NW][2][4][4];
#pragma unroll
    for (int w = 0; w < NW; w++)
#pragma unroll
        for (int a = 0; a < 2; a++)
#pragma unroll
            for (int b = 0; b < 4; b++)
#pragma unroll
                for (int c = 0; c < 4; c++) acc[w][a][b][c] = 0.f;

    // prologue: 3 chunks in flight
    load_buf(0, 0);
    load_buf(1, 1);
    load_buf(2, 2);

    uint32_t aRowOff = (WM * 32 + (lane & 15)) * PITCHB + (lane >> 4) * 16;
    uint32_t bRowOff = (WN * 32 + (lane & 15)) * PITCHB + (lane >> 4) * 16;

    int cb = 0;
    for (int kc = 0; kc < KT; kc++) {
        int inflight = KT - 1 - kc;
        if (inflight >= 2)      { CP_WAIT(2); }
        else if (inflight == 1) { CP_WAIT(1); }
        else                    { CP_WAIT(0); }
        __syncthreads();
        if (kc + 3 < KT) {
            int lb = cb + 3; if (lb >= STAGES) lb -= STAGES;
            load_buf(lb, kc + 3);
        }

        uint32_t base = sb + cb * STAGEB;
#pragma unroll
        for (int ks = 0; ks < 2; ks++) {
            uint32_t kOff = ks * 32;
            uint32_t a[2][4];
#pragma unroll
            for (int mi = 0; mi < 2; mi++)
                ldsm4(a[mi], base + aRowOff + mi * 16 * PITCHB + kOff);
#pragma unroll
            for (int w = 0; w < NW; w++) {
                uint32_t b[2][4];
                uint32_t bBase = base + (1 + w) * PLANEB;
#pragma unroll
                for (int ng = 0; ng < 2; ng++)
                    ldsm4(b[ng], bBase + bRowOff + ng * 16 * PITCHB + kOff);
#pragma unroll
                for (int mi = 0; mi < 2; mi++)
#pragma unroll
                    for (int nj = 0; nj < 4; nj++) {
                        int ng = nj >> 1, ix = nj & 1;
                        mma_f16(acc[w][mi][nj], a[mi], b[ng][ix], b[ng][ix + 2]);
                    }
            }
        }
        cb++; if (cb >= STAGES) cb = 0;
        // no trailing barrier: next iteration's wait+sync provides separation
    }

    // ---- epilogue ----
    int grb = off + r0;
#pragma unroll
    for (int mi = 0; mi < 2; mi++) {
#pragma unroll
        for (int half = 0; half < 2; half++) {
            int r = WM * 32 + mi * 16 + gq + half * 8;
            if (r >= rowsLeft) continue;
            size_t grow = (size_t)(grb + r);
            int tok = 0; float wcomb = 0.f;
            if (MODE == 2) { tok = g_tok[grow]; wcomb = g_wt[grow]; }
#pragma unroll
            for (int nj = 0; nj < 4; nj++) {
                int c = nb + WN * 32 + nj * 8 + tg * 2;
                if (MODE == 0) {
                    float gt0 = acc[0][mi][nj][half * 2 + 0];
                    float gt1 = acc[0][mi][nj][half * 2 + 1];
                    float up0 = acc[1][mi][nj][half * 2 + 0];
                    float up1 = acc[1][mi][nj][half * 2 + 1];
                    float h0 = up0 * gt0 / (1.f + __expf(-gt0));
                    float h1 = up1 * gt1 / (1.f + __expf(-gt1));
                    __half ph0 = __float2half_rn(h0);
                    __half ph1 = __float2half_rn(h1);
                    uint32_t pk = ((uint32_t)__half_as_ushort(ph1) << 16) | __half_as_ushort(ph0);
                    *(uint32_t*)&g_h[grow * HDIM + c] = pk;
                } else {
                    float d0 = acc[0][mi][nj][half * 2 + 0];
                    float d1 = acc[0][mi][nj][half * 2 + 1];
                    float* orow = out + (size_t)tok * CDIM + c;
                    atomicAdd(orow, wcomb * d0);
                    atomicAdd(orow + 1, wcomb * d1);
                }
            }
        }
    }
}

// ---------------- launch (stream-forked graph, balanced branches) -------------
#define SMEM0 (STAGES * 3 * PLANEB)   // 122880
#define SMEM2 (STAGES * 2 * PLANEB)   // 81920

extern "C" void kernel_launch(void* const* d_in, const int* in_sizes, int n_in,
                              void* d_out, int out_size) {
    const float* x      = (const float*)d_in[0];
    const float* w_gate = (const float*)d_in[1];
    const float* wi     = (const float*)d_in[2];
    const float* wg     = (const float*)d_in[3];
    const float* wo     = (const float*)d_in[4];
    float* out = (float*)d_out;

    static cudaStream_t sB = nullptr, sC = nullptr;
    static cudaEvent_t evFork = nullptr, evB = nullptr, evC1 = nullptr, evC2 = nullptr;
    if (sB == nullptr) {
        cudaStreamCreateWithFlags(&sB, cudaStreamNonBlocking);
        cudaStreamCreateWithFlags(&sC, cudaStreamNonBlocking);
        cudaEventCreateWithFlags(&evFork, cudaEventDisableTiming);
        cudaEventCreateWithFlags(&evB, cudaEventDisableTiming);
        cudaEventCreateWithFlags(&evC1, cudaEventDisableTiming);
        cudaEventCreateWithFlags(&evC2, cudaEventDisableTiming);
        cudaFuncSetAttribute(moe_hmma<0>, cudaFuncAttributeMaxDynamicSharedMemorySize, SMEM0);
        cudaFuncSetAttribute(moe_hmma<2>, cudaFuncAttributeMaxDynamicSharedMemorySize, SMEM2);
    }

    // fork: conversion work balanced across two streams, concurrent with routing
    cudaEventRecord(evFork, 0);
    cudaStreamWaitEvent(sB, evFork, 0);
    cudaStreamWaitEvent(sC, evFork, 0);

    dim3 tb(32, 8);
    // stream B: x conversion + wg conversion (needed by hmma<0>)
    xconv_kernel<<<NTOK * CDIM / 1024, 512, 0, sB>>>(x);
    tconv_kernel<0><<<dim3(CDIM / 64, HDIM / 32, NEXP), tb, 0, sB>>>(wg, CDIM, HDIM);
    cudaEventRecord(evB, sB);
    // stream C: wi conversion (needed by hmma<0>), then wo + out-zeroing (hmma<2>)
    tconv_kernel<1><<<dim3(CDIM / 64, HDIM / 32, NEXP), tb, 0, sC>>>(wi, CDIM, HDIM);
    cudaEventRecord(evC1, sC);
    cudaMemsetAsync(out, 0, (size_t)out_size * sizeof(float), sC);
    tconv_kernel<2><<<dim3(HDIM / 64, CDIM / 32, NEXP), tb, 0, sC>>>(wo, HDIM, CDIM);
    cudaEventRecord(evC2, sC);

    // routing chain on the main stream (concurrent with both branches)
    gate_kernel<<<NTOK / 16, 512>>>(x, w_gate);
    route_kernel<<<NEXP, 1024>>>();

    // join x/wg/wi conversions, run fused gate+up GEMM
    cudaStreamWaitEvent(0, evB, 0);
    cudaStreamWaitEvent(0, evC1, 0);
    moe_hmma<0><<<dim3(MT_MAX, HDIM / 128), 512, SMEM0>>>(nullptr);

    // join wo conversion + out zeroing, run down GEMM with fused combine
    cudaStreamWaitEvent(0, evC2, 0);
    moe_hmma<2><<<dim3(MT_MAX, CDIM / 128), 512, SMEM2>>>(out);
}

// round 17
// speedup vs baseline: 1.3222x; 1.0024x over previous
#include <cuda_runtime.h>
#include <cuda_fp16.h>
#include <cstdint>
#include <math.h>

// ---------------- problem constants ------------------------------------------
#define NTOK 8192
#define CDIM 1024
#define HDIM 2048
#define NEXP 8
#define NPAIR (NTOK * 2)
#define BM 128
#define MT_MAX 136

// ---------------- scratch ----------------------------------------------------
__device__ __half g_xh[(size_t)NTOK * CDIM];
__device__ __half g_wgT[(size_t)NEXP * HDIM * CDIM];
__device__ __half g_wiT[(size_t)NEXP * HDIM * CDIM];
__device__ __half g_woT[(size_t)NEXP * CDIM * HDIM];
__device__ __half g_h[(size_t)NPAIR * HDIM];

__device__ int   g_sel[NTOK * 2];
__device__ float g_selw[NTOK * 2];
__device__ int   g_tok[NPAIR];
__device__ float g_wt[NPAIR];
__device__ int   g_cnt[NEXP];
__device__ int   g_off[NEXP];
__device__ int   g_tileE[MT_MAX];
__device__ int   g_tileR[MT_MAX];
__device__ int   g_numTiles;

// ---------------- PTX helpers -------------------------------------------------
__device__ __forceinline__ uint32_t smem_u32(const void* p) {
    uint32_t a;
    asm("{ .reg .u64 t; cvta.to.shared.u64 t, %1; cvt.u32.u64 %0, t; }" : "=r"(a) : "l"(p));
    return a;
}
__device__ __forceinline__ void ldsm4(uint32_t* r, uint32_t addr) {
    asm volatile("ldmatrix.sync.aligned.m8n8.x4.shared.b16 {%0,%1,%2,%3}, [%4];"
                 : "=r"(r[0]), "=r"(r[1]), "=r"(r[2]), "=r"(r[3]) : "r"(addr));
}
__device__ __forceinline__ void mma_f16(float* d, const uint32_t* a, uint32_t b0, uint32_t b1) {
    asm volatile("mma.sync.aligned.m16n8k16.row.col.f32.f16.f16.f32 "
                 "{%0,%1,%2,%3}, {%4,%5,%6,%7}, {%8,%9}, {%0,%1,%2,%3};"
                 : "+f"(d[0]), "+f"(d[1]), "+f"(d[2]), "+f"(d[3])
                 : "r"(a[0]), "r"(a[1]), "r"(a[2]), "r"(a[3]), "r"(b0), "r"(b1));
}
#define CP_ASYNC16(dst, src, sz) \
    asm volatile("cp.async.cg.shared.global [%0], [%1], 16, %2;" :: "r"(dst), "l"(src), "r"(sz) : "memory")
#define CP_COMMIT() asm volatile("cp.async.commit_group;" ::: "memory")
#define CP_WAIT(n)  asm volatile("cp.async.wait_group %0;" :: "n"(n) : "memory")

// ---------------- gating (512 thr, 16 tokens/block, smem wgate^T) -------------
#define WPITCH 1028
__global__ void gate_kernel(const float* __restrict__ x, const float* __restrict__ wgate) {
    __shared__ float swT[NEXP * WPITCH];
    int tid = threadIdx.x;
    for (int i = tid; i < CDIM * NEXP; i += 512) {
        int c = i >> 3, e = i & 7;
        swT[e * WPITCH + c] = wgate[i];
    }
    __syncthreads();

    int warp = blockIdx.x * 16 + (tid >> 5);
    int lane = tid & 31;
    const float* xr = x + (size_t)warp * CDIM;

    float acc[NEXP];
#pragma unroll
    for (int e = 0; e < NEXP; e++) acc[e] = 0.f;
#pragma unroll
    for (int i = lane * 4; i < CDIM; i += 128) {
        float4 xv = *(const float4*)(xr + i);
#pragma unroll
        for (int e = 0; e < NEXP; e++) {
            float4 wv = *(const float4*)&swT[e * WPITCH + i];
            acc[e] += xv.x * wv.x + xv.y * wv.y + xv.z * wv.z + xv.w * wv.w;
        }
    }
#pragma unroll
    for (int e = 0; e < NEXP; e++)
#pragma unroll
        for (int d = 16; d > 0; d >>= 1) acc[e] += __shfl_down_sync(0xffffffffu, acc[e], d);
    if (lane == 0) {
        float m = acc[0];
#pragma unroll
        for (int e = 1; e < NEXP; e++) m = fmaxf(m, acc[e]);
        float p[NEXP]; float s = 0.f;
#pragma unroll
        for (int e = 0; e < NEXP; e++) { p[e] = expf(acc[e] - m); s += p[e]; }
        float inv = 1.f / s;
#pragma unroll
        for (int e = 0; e < NEXP; e++) p[e] *= inv;
        int i1 = 0;
#pragma unroll
        for (int e = 1; e < NEXP; e++) if (p[e] > p[i1]) i1 = e;
        int i2 = (i1 == 0) ? 1 : 0;
#pragma unroll
        for (int e = 0; e < NEXP; e++) if (e != i1 && p[e] > p[i2]) i2 = e;
        g_sel[2 * warp] = i1;     g_selw[2 * warp] = p[i1];
        g_sel[2 * warp + 1] = i2; g_selw[2 * warp + 1] = p[i2];
    }
}

// ---------------- routing: single fused kernel --------------------------------
__global__ void route_kernel() {
    __shared__ int scnt[NEXP][32];
    __shared__ int tot[NEXP];
    __shared__ int wsum[32];
    __shared__ int carry;
    int e = blockIdx.x;
    int tid = threadIdx.x, lane = tid & 31, wid = tid >> 5;

    int c[NEXP] = {0, 0, 0, 0, 0, 0, 0, 0};
    for (int t = tid; t < NTOK; t += 1024) {
        int s0 = g_sel[2 * t], s1 = g_sel[2 * t + 1];
#pragma unroll
        for (int k = 0; k < NEXP; k++) c[k] += (s0 == k) + (s1 == k);
    }
#pragma unroll
    for (int k = 0; k < NEXP; k++) {
#pragma unroll
        for (int d = 16; d > 0; d >>= 1) c[k] += __shfl_down_sync(0xffffffffu, c[k], d);
        if (lane == 0) scnt[k][wid] = c[k];
    }
    __syncthreads();
    if (wid < NEXP) {
        int v = scnt[wid][lane];
#pragma unroll
        for (int d = 16; d > 0; d >>= 1) v += __shfl_down_sync(0xffffffffu, v, d);
        if (lane == 0) tot[wid] = v;
    }
    __syncthreads();

    int base_off = 0;
#pragma unroll
    for (int k = 0; k < NEXP; k++) if (k < e) base_off += tot[k];
    if (tid == 0) { g_cnt[e] = tot[e]; g_off[e] = base_off; carry = 0; }
    if (e == 0 && tid == 0) {
        int nt = 0;
        for (int k = 0; k < NEXP; k++)
            for (int r = 0; r < tot[k]; r += BM) { g_tileE[nt] = k; g_tileR[nt] = r; nt++; }
        g_numTiles = nt;
    }
    __syncthreads();

    for (int base = 0; base < NTOK; base += 1024) {
        int t = base + tid;
        int slot = (g_sel[2 * t] == e) ? 0 : ((g_sel[2 * t + 1] == e) ? 1 : -1);
        int f = (slot >= 0) ? 1 : 0;
        int v = f;
#pragma unroll
        for (int d = 1; d < 32; d <<= 1) {
            int u = __shfl_up_sync(0xffffffffu, v, d);
            if (lane >= d) v += u;
        }
        if (lane == 31) wsum[wid] = v;
        __syncthreads();
        int wbase = 0, totb = 0;
#pragma unroll
        for (int w = 0; w < 32; w++) { if (w < wid) wbase += wsum[w]; totb += wsum[w]; }
        if (f) {
            int p = base_off + carry + wbase + v - 1;
            g_tok[p] = t;
            g_wt[p] = g_selw[2 * t + slot];
        }
        __syncthreads();
        if (tid == 0) carry += totb;
        __syncthreads();
    }
}

// ---------------- x -> fp16 ----------------------------------------------------
__global__ void xconv_kernel(const float* __restrict__ x) {
    size_t i = (size_t)blockIdx.x * 512 + threadIdx.x;
    float2 v = ((const float2*)x)[i];
    ((__half2*)g_xh)[i] = __floats2half2_rn(v.x, v.y);
}

// ---------------- weight transpose + fp16 -------------------------------------
template <int W>
__global__ void tconv_kernel(const float* __restrict__ src, int K, int S) {
    __half* dst = (W == 0) ? g_wgT : (W == 1) ? g_wiT : g_woT;
    __shared__ float t[64][33];
    int e = blockIdx.z;
    int k0 = blockIdx.x * 64, s0 = blockIdx.y * 32;
    const float* sp = src + (size_t)e * K * S;
    int tx = threadIdx.x, ty = threadIdx.y;
#pragma unroll
    for (int j = 0; j < 64; j += 8)
        t[ty + j][tx] = sp[(size_t)(k0 + ty + j) * S + s0 + tx];
    __syncthreads();
    size_t dbase = (size_t)e * S * K;
#pragma unroll
    for (int j = 0; j < 32; j += 8) {
        int s = s0 + ty + j;
        __half2 h = __floats2half2_rn(t[tx * 2][ty + j], t[tx * 2 + 1][ty + j]);
        *(__half2*)&dst[dbase + (size_t)s * K + k0 + tx * 2] = h;
    }
}

// ---------------- fp16 mma GEMM, 128x128 tile, multistage cp.async ------------
// MODE 0: gate/up fused -> g_h. BK=32, pitch 80B, 4 stages.
// MODE 2: down + fused combine (atomicAdd). BK=64, pitch 272B, 3 stages —
//         halves the per-chunk wait/barrier/issue rounds on the K=2048 loop.
template <int MODE>
__global__ void __launch_bounds__(512, 1)
moe_hmma(float* __restrict__ out) {
    constexpr int K = (MODE == 0) ? CDIM : HDIM;
    constexpr int BK = (MODE == 0) ? 32 : 64;
    constexpr int KT = K / BK;
    constexpr int NW = (MODE == 0) ? 2 : 1;
    constexpr int PITCH = (MODE == 0) ? 80 : 272;        // bytes per row (+pad)
    constexpr int PLANE = 128 * PITCH;
    constexpr int STAGEB = (1 + NW) * PLANE;
    constexpr int NSTG = (MODE == 0) ? 4 : 3;
    constexpr int KSN = BK / 16;                         // k-steps per chunk
    constexpr int CH_ROW = BK / 8;                       // 16B chunks per row
    constexpr int ITER = (128 * CH_ROW) / 512;           // chunks per thread/plane

    extern __shared__ char smem[];
    uint32_t sb = smem_u32(smem);

    int bx = blockIdx.x;
    if (bx >= g_numTiles) return;
    int by = blockIdx.y;
    int e = g_tileE[bx], r0 = g_tileR[bx], off = g_off[e];
    int rowsLeft = g_cnt[e] - r0;
    if (rowsLeft > 128) rowsLeft = 128;
    int nb = by * 128;

    int tid = threadIdx.x, wid = tid >> 5, lane = tid & 31;
    int WM = wid & 3, WN = wid >> 2;
    int gq = lane >> 2, tg = lane & 3;

    const __half* srcB[2];
    if (MODE == 0) {
        srcB[0] = g_wgT + ((size_t)e * HDIM + nb) * CDIM;
        srcB[1] = g_wiT + ((size_t)e * HDIM + nb) * CDIM;
    } else {
        srcB[0] = g_woT + ((size_t)e * CDIM + nb) * HDIM;
    }

    // MODE0: one chunk/thread/plane with token indirection resolved once.
    const __half* aRowPtr0 = nullptr;
    uint32_t szA0 = 0;
    if (MODE == 0) {
        int lrow = tid >> 2;
        bool aval = lrow < rowsLeft;
        int tok = g_tok[off + r0 + (aval ? lrow : 0)];
        aRowPtr0 = g_xh + (size_t)tok * CDIM;
        szA0 = aval ? 16u : 0u;
    }

    auto load_buf = [&](int buf, int kc) {
        uint32_t base = sb + buf * STAGEB;
        int k0 = kc * BK;
#pragma unroll
        for (int i = 0; i < ITER; i++) {
            int idx = tid + 512 * i;
            int row = idx / CH_ROW;
            int ch = idx % CH_ROW;
            uint32_t doff = row * PITCH + ch * 16;
            if (MODE == 0) {
                CP_ASYNC16(base + doff, aRowPtr0 + k0 + ch * 8, szA0);
            } else {
                bool aval = row < rowsLeft;
                const __half* asrc = g_h + (size_t)(off + r0 + (aval ? row : 0)) * HDIM + k0 + ch * 8;
                CP_ASYNC16(base + doff, asrc, aval ? 16u : 0u);
            }
#pragma unroll
            for (int p = 0; p < NW; p++)
                CP_ASYNC16(base + (1 + p) * PLANE + doff,
                           srcB[p] + (size_t)row * K + k0 + ch * 8, 16u);
        }
        CP_COMMIT();
    };

    float acc[NW][2][4][4];
#pragma unroll
    for (int w = 0; w < NW; w++)
#pragma unroll
        for (int a = 0; a < 2; a++)
#pragma unroll
            for (int b = 0; b < 4; b++)
#pragma unroll
                for (int c = 0; c < 4; c++) acc[w][a][b][c] = 0.f;

    // prologue: NSTG-1 chunks in flight
#pragma unroll
    for (int s = 0; s < NSTG - 1; s++) load_buf(s, s);

    uint32_t aRowOff = (WM * 32 + (lane & 15)) * PITCH + (lane >> 4) * 16;
    uint32_t bRowOff = (WN * 32 + (lane & 15)) * PITCH + (lane >> 4) * 16;

    int cb = 0;
    for (int kc = 0; kc < KT; kc++) {
        int rem = KT - 1 - kc;
        int pend = (NSTG - 2 < rem) ? (NSTG - 2) : rem;
        if (pend >= 2)      { CP_WAIT(2); }
        else if (pend == 1) { CP_WAIT(1); }
        else                { CP_WAIT(0); }
        __syncthreads();
        if (kc + NSTG - 1 < KT) {
            int lb = cb + NSTG - 1; if (lb >= NSTG) lb -= NSTG;
            load_buf(lb, kc + NSTG - 1);
        }

        uint32_t base = sb + cb * STAGEB;
#pragma unroll
        for (int ks = 0; ks < KSN; ks++) {
            uint32_t kOff = ks * 32;
            uint32_t a[2][4];
#pragma unroll
            for (int mi = 0; mi < 2; mi++)
                ldsm4(a[mi], base + aRowOff + mi * 16 * PITCH + kOff);
#pragma unroll
            for (int w = 0; w < NW; w++) {
                uint32_t b[2][4];
                uint32_t bBase = base + (1 + w) * PLANE;
#pragma unroll
                for (int ng = 0; ng < 2; ng++)
                    ldsm4(b[ng], bBase + bRowOff + ng * 16 * PITCH + kOff);
#pragma unroll
                for (int mi = 0; mi < 2; mi++)
#pragma unroll
                    for (int nj = 0; nj < 4; nj++) {
                        int ng = nj >> 1, ix = nj & 1;
                        mma_f16(acc[w][mi][nj], a[mi], b[ng][ix], b[ng][ix + 2]);
                    }
            }
        }
        cb++; if (cb >= NSTG) cb = 0;
        // no trailing barrier: next iteration's wait+sync provides separation
    }

    // ---- epilogue ----
    int grb = off + r0;
#pragma unroll
    for (int mi = 0; mi < 2; mi++) {
#pragma unroll
        for (int half = 0; half < 2; half++) {
            int r = WM * 32 + mi * 16 + gq + half * 8;
            if (r >= rowsLeft) continue;
            size_t grow = (size_t)(grb + r);
            int tok = 0; float wcomb = 0.f;
            if (MODE == 2) { tok = g_tok[grow]; wcomb = g_wt[grow]; }
#pragma unroll
            for (int nj = 0; nj < 4; nj++) {
                int c = nb + WN * 32 + nj * 8 + tg * 2;
                if (MODE == 0) {
                    float gt0 = acc[0][mi][nj][half * 2 + 0];
                    float gt1 = acc[0][mi][nj][half * 2 + 1];
                    float up0 = acc[1][mi][nj][half * 2 + 0];
                    float up1 = acc[1][mi][nj][half * 2 + 1];
                    float h0 = up0 * gt0 / (1.f + __expf(-gt0));
                    float h1 = up1 * gt1 / (1.f + __expf(-gt1));
                    __half ph0 = __float2half_rn(h0);
                    __half ph1 = __float2half_rn(h1);
                    uint32_t pk = ((uint32_t)__half_as_ushort(ph1) << 16) | __half_as_ushort(ph0);
                    *(uint32_t*)&g_h[grow * HDIM + c] = pk;
                } else {
                    float d0 = acc[0][mi][nj][half * 2 + 0];
                    float d1 = acc[0][mi][nj][half * 2 + 1];
                    float* orow = out + (size_t)tok * CDIM + c;
                    atomicAdd(orow, wcomb * d0);
                    atomicAdd(orow + 1, wcomb * d1);
                }
            }
        }
    }
}

// ---------------- launch (stream-forked graph, balanced branches) -------------
#define SMEM0 (4 * 3 * 128 * 80)    // 122880
#define SMEM2 (3 * 2 * 128 * 272)   // 208896

extern "C" void kernel_launch(void* const* d_in, const int* in_sizes, int n_in,
                              void* d_out, int out_size) {
    const float* x      = (const float*)d_in[0];
    const float* w_gate = (const float*)d_in[1];
    const float* wi     = (const float*)d_in[2];
    const float* wg     = (const float*)d_in[3];
    const float* wo     = (const float*)d_in[4];
    float* out = (float*)d_out;

    static cudaStream_t sB = nullptr, sC = nullptr;
    static cudaEvent_t evFork = nullptr, evB = nullptr, evC1 = nullptr, evC2 = nullptr;
    if (sB == nullptr) {
        cudaStreamCreateWithFlags(&sB, cudaStreamNonBlocking);
        cudaStreamCreateWithFlags(&sC, cudaStreamNonBlocking);
        cudaEventCreateWithFlags(&evFork, cudaEventDisableTiming);
        cudaEventCreateWithFlags(&evB, cudaEventDisableTiming);
        cudaEventCreateWithFlags(&evC1, cudaEventDisableTiming);
        cudaEventCreateWithFlags(&evC2, cudaEventDisableTiming);
        cudaFuncSetAttribute(moe_hmma<0>, cudaFuncAttributeMaxDynamicSharedMemorySize, SMEM0);
        cudaFuncSetAttribute(moe_hmma<2>, cudaFuncAttributeMaxDynamicSharedMemorySize, SMEM2);
    }

    // fork: conversion work balanced across two streams, concurrent with routing
    cudaEventRecord(evFork, 0);
    cudaStreamWaitEvent(sB, evFork, 0);
    cudaStreamWaitEvent(sC, evFork, 0);

    dim3 tb(32, 8);
    xconv_kernel<<<NTOK * CDIM / 1024, 512, 0, sB>>>(x);
    tconv_kernel<0><<<dim3(CDIM / 64, HDIM / 32, NEXP), tb, 0, sB>>>(wg, CDIM, HDIM);
    cudaEventRecord(evB, sB);
    tconv_kernel<1><<<dim3(CDIM / 64, HDIM / 32, NEXP), tb, 0, sC>>>(wi, CDIM, HDIM);
    cudaEventRecord(evC1, sC);
    cudaMemsetAsync(out, 0, (size_t)out_size * sizeof(float), sC);
    tconv_kernel<2><<<dim3(HDIM / 64, CDIM / 32, NEXP), tb, 0, sC>>>(wo, HDIM, CDIM);
    cudaEventRecord(evC2, sC);

    // routing chain on the main stream (concurrent with both branches)
    gate_kernel<<<NTOK / 16, 512>>>(x, w_gate);
    route_kernel<<<NEXP, 1024>>>();

    // join x/wg/wi conversions, run fused gate+up GEMM
    cudaStreamWaitEvent(0, evB, 0);
    cudaStreamWaitEvent(0, evC1, 0);
    moe_hmma<0><<<dim3(MT_MAX, HDIM / 128), 512, SMEM0>>>(nullptr);

    // join wo conversion + out zeroing, run down GEMM with fused combine
    cudaStreamWaitEvent(0, evC2, 0);
    moe_hmma<2><<<dim3(MT_MAX, CDIM / 128), 512, SMEM2>>>(out);
}